// round 1
// baseline (speedup 1.0000x reference)
#include <cuda_runtime.h>
#include <cuda_bf16.h>
#include <cstdint>
#include <math.h>

// Problem constants
#define BATCH 16
#define SEQ   512
#define DMODEL 1024
#define NHEAD 16
#define DK    64   // DMODEL / NHEAD

// ---------------------------------------------------------------------------
// Scratch (no cudaMalloc allowed) — __device__ globals
// ---------------------------------------------------------------------------
__device__ float g_Q[(size_t)BATCH * SEQ * DMODEL];     // 32 MB, layout [b,s,h,d]
__device__ float g_K[(size_t)BATCH * SEQ * DMODEL];     // 32 MB
__device__ float g_V[(size_t)BATCH * SEQ * DMODEL];     // 32 MB
__device__ float g_ctx[(size_t)BATCH * SEQ * DMODEL];   // 32 MB
__device__ float g_attn[(size_t)BATCH * NHEAD * SEQ * SEQ]; // 256 MB, [b,h,s,t]

// ---------------------------------------------------------------------------
// SGEMM: C[M,N] = A[M,K] @ W[N,K]^T + bias[N]
// BM=BN=128, BK=16, 256 threads, 8x8 per thread. M,N,K multiples of tile dims.
// ---------------------------------------------------------------------------
#define GBM 128
#define GBN 128
#define GBK 16
#define GTM 8
#define GTN 8

__global__ void __launch_bounds__(256)
sgemm_nt_bias(const float* __restrict__ A, const float* __restrict__ W,
              const float* __restrict__ bias, float* __restrict__ C,
              int M, int N, int K)
{
    __shared__ float As[GBK][GBM];
    __shared__ float Bs[GBK][GBN];

    const int tid  = threadIdx.x;
    const int brow = blockIdx.y * GBM;
    const int bcol = blockIdx.x * GBN;
    const int tx = tid & 15;        // 0..15
    const int ty = tid >> 4;        // 0..15

    float acc[GTM][GTN];
#pragma unroll
    for (int m = 0; m < GTM; m++)
#pragma unroll
        for (int n = 0; n < GTN; n++) acc[m][n] = 0.f;

    // loader mapping: each thread loads 2 float4 from A and 2 from W per k-step
    const int lrow = tid >> 2;        // 0..63
    const int lk4  = (tid & 3) * 4;   // 0,4,8,12
    const float* Ap = A + (size_t)(brow + lrow) * K + lk4;
    const float* Wp = W + (size_t)(bcol + lrow) * K + lk4;

    for (int k0 = 0; k0 < K; k0 += GBK) {
#pragma unroll
        for (int hh = 0; hh < 2; hh++) {
            float4 va = *reinterpret_cast<const float4*>(Ap + (size_t)hh * 64 * K + k0);
            As[lk4 + 0][lrow + hh * 64] = va.x;
            As[lk4 + 1][lrow + hh * 64] = va.y;
            As[lk4 + 2][lrow + hh * 64] = va.z;
            As[lk4 + 3][lrow + hh * 64] = va.w;
            float4 vb = *reinterpret_cast<const float4*>(Wp + (size_t)hh * 64 * K + k0);
            Bs[lk4 + 0][lrow + hh * 64] = vb.x;
            Bs[lk4 + 1][lrow + hh * 64] = vb.y;
            Bs[lk4 + 2][lrow + hh * 64] = vb.z;
            Bs[lk4 + 3][lrow + hh * 64] = vb.w;
        }
        __syncthreads();

#pragma unroll
        for (int kk = 0; kk < GBK; kk++) {
            float4 a0 = *reinterpret_cast<const float4*>(&As[kk][ty * GTM]);
            float4 a1 = *reinterpret_cast<const float4*>(&As[kk][ty * GTM + 4]);
            float4 b0 = *reinterpret_cast<const float4*>(&Bs[kk][tx * GTN]);
            float4 b1 = *reinterpret_cast<const float4*>(&Bs[kk][tx * GTN + 4]);
            float ra[GTM] = {a0.x, a0.y, a0.z, a0.w, a1.x, a1.y, a1.z, a1.w};
            float rb[GTN] = {b0.x, b0.y, b0.z, b0.w, b1.x, b1.y, b1.z, b1.w};
#pragma unroll
            for (int m = 0; m < GTM; m++)
#pragma unroll
                for (int n = 0; n < GTN; n++)
                    acc[m][n] = fmaf(ra[m], rb[n], acc[m][n]);
        }
        __syncthreads();
    }

    // epilogue with bias
    float bi[GTN];
#pragma unroll
    for (int n = 0; n < GTN; n++) bi[n] = bias[bcol + tx * GTN + n];

#pragma unroll
    for (int m = 0; m < GTM; m++) {
        int row = brow + ty * GTM + m;
        float* cp = C + (size_t)row * N + bcol + tx * GTN;
        float4 o0 = make_float4(acc[m][0] + bi[0], acc[m][1] + bi[1],
                                acc[m][2] + bi[2], acc[m][3] + bi[3]);
        float4 o1 = make_float4(acc[m][4] + bi[4], acc[m][5] + bi[5],
                                acc[m][6] + bi[6], acc[m][7] + bi[7]);
        *reinterpret_cast<float4*>(cp)     = o0;
        *reinterpret_cast<float4*>(cp + 4) = o1;
    }
}

// ---------------------------------------------------------------------------
// scores[b,h,s,t] = QK^T/8 + rel_bias, causal-masked. 64x64 tiles, K=64 one shot.
// Fully-masked tiles (t0 > s0+63) are skipped — softmax never reads t > s.
// ---------------------------------------------------------------------------
__global__ void __launch_bounds__(256)
scores_kernel(const float* __restrict__ rel_bias)
{
    const int bh = blockIdx.z;
    const int b  = bh >> 4;           // / NHEAD
    const int h  = bh & 15;
    const int s0 = blockIdx.y * 64;
    const int t0 = blockIdx.x * 64;
    if (t0 > s0 + 63) return;         // fully above diagonal

    __shared__ float Qs[64][68];      // [d][s]
    __shared__ float Ks[64][68];      // [d][t]

    const int tid = threadIdx.x;
    const float* Qb = g_Q + ((size_t)b * SEQ + s0) * DMODEL + h * DK;
    const float* Kb = g_K + ((size_t)b * SEQ + t0) * DMODEL + h * DK;

#pragma unroll
    for (int i = 0; i < 4; i++) {
        int f  = tid + i * 256;       // 0..1023
        int r  = f >> 4;              // row 0..63
        int dg = (f & 15) * 4;        // d group
        float4 q = *reinterpret_cast<const float4*>(Qb + (size_t)r * DMODEL + dg);
        Qs[dg + 0][r] = q.x; Qs[dg + 1][r] = q.y;
        Qs[dg + 2][r] = q.z; Qs[dg + 3][r] = q.w;
        float4 kv = *reinterpret_cast<const float4*>(Kb + (size_t)r * DMODEL + dg);
        Ks[dg + 0][r] = kv.x; Ks[dg + 1][r] = kv.y;
        Ks[dg + 2][r] = kv.z; Ks[dg + 3][r] = kv.w;
    }
    __syncthreads();

    const int tx = tid & 15;
    const int ty = tid >> 4;
    float acc[4][4];
#pragma unroll
    for (int m = 0; m < 4; m++)
#pragma unroll
        for (int n = 0; n < 4; n++) acc[m][n] = 0.f;

#pragma unroll
    for (int d = 0; d < 64; d++) {
        float4 rq = *reinterpret_cast<const float4*>(&Qs[d][ty * 4]);
        float4 rk = *reinterpret_cast<const float4*>(&Ks[d][tx * 4]);
        float ra[4] = {rq.x, rq.y, rq.z, rq.w};
        float rb[4] = {rk.x, rk.y, rk.z, rk.w};
#pragma unroll
        for (int m = 0; m < 4; m++)
#pragma unroll
            for (int n = 0; n < 4; n++)
                acc[m][n] = fmaf(ra[m], rb[n], acc[m][n]);
    }

    const float inv_scale = 0.125f;   // 1/sqrt(64)
    float* arow = g_attn + ((size_t)bh * SEQ) * SEQ;
#pragma unroll
    for (int m = 0; m < 4; m++) {
        int s = s0 + ty * 4 + m;
        const float* rb_ptr = rel_bias + ((size_t)h * SEQ + s) * SEQ;
        float* wr = arow + (size_t)s * SEQ;
#pragma unroll
        for (int n = 0; n < 4; n++) {
            int t = t0 + tx * 4 + n;
            float v = (t <= s) ? (acc[m][n] * inv_scale + rb_ptr[t]) : -INFINITY;
            wr[t] = v;
        }
    }
}

// ---------------------------------------------------------------------------
// Row softmax, in place; writes exact zeros for t > s.
// One block (256 thr) per (bh, s). Row length SEQ=512.
// ---------------------------------------------------------------------------
__device__ __forceinline__ float warpMaxf(float v) {
#pragma unroll
    for (int o = 16; o; o >>= 1) v = fmaxf(v, __shfl_xor_sync(0xffffffffu, v, o));
    return v;
}
__device__ __forceinline__ float warpSumf(float v) {
#pragma unroll
    for (int o = 16; o; o >>= 1) v += __shfl_xor_sync(0xffffffffu, v, o);
    return v;
}

__global__ void __launch_bounds__(256)
softmax_kernel()
{
    const int s  = blockIdx.x;
    const int bh = blockIdx.y;
    float* row = g_attn + ((size_t)bh * SEQ + s) * SEQ;
    const int tid = threadIdx.x;
    const int L = s + 1;

    __shared__ float red[8];

    int t0 = tid, t1 = tid + 256;
    float v0 = (t0 < L) ? row[t0] : -INFINITY;
    float v1 = (t1 < L) ? row[t1] : -INFINITY;

    float mx = warpMaxf(fmaxf(v0, v1));
    if ((tid & 31) == 0) red[tid >> 5] = mx;
    __syncthreads();
    if (tid < 8) { float t = red[tid]; t = fmaxf(t, __shfl_xor_sync(0xffu, t, 4));
                   t = fmaxf(t, __shfl_xor_sync(0xffu, t, 2));
                   t = fmaxf(t, __shfl_xor_sync(0xffu, t, 1)); red[tid] = t; }
    __syncthreads();
    mx = red[0];

    float e0 = (t0 < L) ? __expf(v0 - mx) : 0.f;
    float e1 = (t1 < L) ? __expf(v1 - mx) : 0.f;
    float sm = warpSumf(e0 + e1);
    __syncthreads();
    if ((tid & 31) == 0) red[tid >> 5] = sm;
    __syncthreads();
    if (tid < 8) { float t = red[tid]; t += __shfl_xor_sync(0xffu, t, 4);
                   t += __shfl_xor_sync(0xffu, t, 2);
                   t += __shfl_xor_sync(0xffu, t, 1); red[tid] = t; }
    __syncthreads();
    float inv = 1.f / red[0];

    row[t0] = e0 * inv;
    row[t1] = e1 * inv;
}

// ---------------------------------------------------------------------------
// attn head-mean: out2[b,s,t] = (1/H) sum_h attn[b,h,s,t]
// ---------------------------------------------------------------------------
__global__ void __launch_bounds__(256)
mean_kernel(float* __restrict__ out2)
{
    const size_t idx = (size_t)blockIdx.x * 256 + threadIdx.x;
    const size_t SS = (size_t)SEQ * SEQ;
    const int b = (int)(idx / SS);
    const size_t r = idx % SS;
    const float* base = g_attn + (size_t)b * NHEAD * SS + r;
    float sum = 0.f;
#pragma unroll
    for (int h = 0; h < NHEAD; h++) sum += base[(size_t)h * SS];
    out2[idx] = sum * (1.f / NHEAD);
}

// ---------------------------------------------------------------------------
// ctx[b,s,h,d] = sum_t attn[b,h,s,t] * V[b,t,h,d]. Per (b,h): [512x512]@[512x64].
// BM=64, BN=64(=DK), BK=16, causal-truncated K loop.
// ---------------------------------------------------------------------------
__global__ void __launch_bounds__(256)
ctx_kernel()
{
    const int bh = blockIdx.z;
    const int b  = bh >> 4;
    const int h  = bh & 15;
    const int s0 = blockIdx.y * 64;

    __shared__ float As[16][68];   // [k][s]
    __shared__ float Bs[16][68];   // [k][d]

    const int tid = threadIdx.x;
    const int tx = tid & 15;
    const int ty = tid >> 4;

    const float* Arow = g_attn + ((size_t)bh * SEQ) * SEQ;  // [s][t]
    const float* Vb   = g_V + (size_t)b * SEQ * DMODEL + h * DK;

    float acc[4][4];
#pragma unroll
    for (int m = 0; m < 4; m++)
#pragma unroll
        for (int n = 0; n < 4; n++) acc[m][n] = 0.f;

    const int kmax = s0 + 64;   // attn is zero beyond the diagonal
    // loader mappings
    const int ar = tid >> 2;          // 0..63 (attn row)
    const int ak = (tid & 3) * 4;     // k group
    const int vr = tid >> 4;          // 0..15 (V k-row)
    const int vc = (tid & 15) * 4;    // d group

    for (int k0 = 0; k0 < kmax; k0 += 16) {
        float4 av = *reinterpret_cast<const float4*>(Arow + (size_t)(s0 + ar) * SEQ + k0 + ak);
        As[ak + 0][ar] = av.x; As[ak + 1][ar] = av.y;
        As[ak + 2][ar] = av.z; As[ak + 3][ar] = av.w;
        float4 vv = *reinterpret_cast<const float4*>(Vb + (size_t)(k0 + vr) * DMODEL + vc);
        Bs[vr][vc + 0] = vv.x; Bs[vr][vc + 1] = vv.y;
        Bs[vr][vc + 2] = vv.z; Bs[vr][vc + 3] = vv.w;
        __syncthreads();

#pragma unroll
        for (int kk = 0; kk < 16; kk++) {
            float4 ra4 = *reinterpret_cast<const float4*>(&As[kk][ty * 4]);
            float4 rb4 = *reinterpret_cast<const float4*>(&Bs[kk][tx * 4]);
            float ra[4] = {ra4.x, ra4.y, ra4.z, ra4.w};
            float rb[4] = {rb4.x, rb4.y, rb4.z, rb4.w};
#pragma unroll
            for (int m = 0; m < 4; m++)
#pragma unroll
                for (int n = 0; n < 4; n++)
                    acc[m][n] = fmaf(ra[m], rb[n], acc[m][n]);
        }
        __syncthreads();
    }

#pragma unroll
    for (int m = 0; m < 4; m++) {
        int s = s0 + ty * 4 + m;
        float* cp = g_ctx + ((size_t)b * SEQ + s) * DMODEL + h * DK + tx * 4;
        float4 o = make_float4(acc[m][0], acc[m][1], acc[m][2], acc[m][3]);
        *reinterpret_cast<float4*>(cp) = o;
    }
}

// ---------------------------------------------------------------------------
// Launch
// ---------------------------------------------------------------------------
extern "C" void kernel_launch(void* const* d_in, const int* in_sizes, int n_in,
                              void* d_out, int out_size)
{
    const float* query = (const float*)d_in[0];
    const float* key   = (const float*)d_in[1];
    const float* value = (const float*)d_in[2];
    const float* wq_w  = (const float*)d_in[3];
    const float* wq_b  = (const float*)d_in[4];
    const float* wk_w  = (const float*)d_in[5];
    const float* wk_b  = (const float*)d_in[6];
    const float* wv_w  = (const float*)d_in[7];
    const float* wv_b  = (const float*)d_in[8];
    const float* wo_w  = (const float*)d_in[9];
    const float* wo_b  = (const float*)d_in[10];
    const float* rel_bias = (const float*)d_in[11];

    float* out  = (float*)d_out;
    const size_t out1_elems = (size_t)BATCH * SEQ * DMODEL;          // 8388608
    const size_t out2_elems = (size_t)BATCH * SEQ * SEQ;             // 4194304
    float* out2 = out + out1_elems;

    float *qP, *kP, *vP, *cP;
    cudaGetSymbolAddress((void**)&qP, g_Q);
    cudaGetSymbolAddress((void**)&kP, g_K);
    cudaGetSymbolAddress((void**)&vP, g_V);
    cudaGetSymbolAddress((void**)&cP, g_ctx);

    const int M = BATCH * SEQ;      // 8192
    const int N = DMODEL;           // 1024
    const int K = DMODEL;           // 1024
    dim3 gP(N / GBN, M / GBM);      // (8, 64)

    sgemm_nt_bias<<<gP, 256>>>(query, wq_w, wq_b, qP, M, N, K);
    sgemm_nt_bias<<<gP, 256>>>(key,   wk_w, wk_b, kP, M, N, K);
    sgemm_nt_bias<<<gP, 256>>>(value, wv_w, wv_b, vP, M, N, K);

    scores_kernel<<<dim3(SEQ / 64, SEQ / 64, BATCH * NHEAD), 256>>>(rel_bias);
    softmax_kernel<<<dim3(SEQ, BATCH * NHEAD), 256>>>();

    if ((size_t)out_size >= out1_elems + out2_elems) {
        mean_kernel<<<(unsigned)(out2_elems / 256), 256>>>(out2);
    }

    ctx_kernel<<<dim3(1, SEQ / 64, BATCH * NHEAD), 256>>>();
    sgemm_nt_bias<<<gP, 256>>>(cP, wo_w, wo_b, out, M, N, K);
}

// round 3
// speedup vs baseline: 1.5862x; 1.5862x over previous
#include <cuda_runtime.h>
#include <cuda_bf16.h>
#include <cstdint>
#include <math.h>

// Problem constants
#define BATCH 16
#define SEQ   512
#define DMODEL 1024
#define NHEAD 16
#define DK    64

// ===========================================================================
// Portable PTX helpers (no sm_103a-only instructions!)
// ===========================================================================
__device__ __forceinline__ uint32_t smem_to_u32(const void* p) {
    uint32_t a;
    asm("{ .reg .u64 t; cvta.to.shared.u64 t, %1; cvt.u32.u64 %0, t; }" : "=r"(a) : "l"(p));
    return a;
}
__device__ __forceinline__ void cp_async16(uint32_t smem_addr, const void* gptr) {
    asm volatile("cp.async.cg.shared.global [%0], [%1], 16;" :: "r"(smem_addr), "l"(gptr) : "memory");
}
__device__ __forceinline__ void cp_commit() { asm volatile("cp.async.commit_group;" ::: "memory"); }
__device__ __forceinline__ void cp_wait1()  { asm volatile("cp.async.wait_group 1;" ::: "memory"); }
__device__ __forceinline__ void cp_wait0()  { asm volatile("cp.async.wait_group 0;" ::: "memory"); }

#define LDSM_X4(r0, r1, r2, r3, addr) \
    asm volatile("ldmatrix.sync.aligned.m8n8.x4.shared.b16 {%0,%1,%2,%3}, [%4];" \
        : "=r"(r0), "=r"(r1), "=r"(r2), "=r"(r3) : "r"(addr))

#define MMA16816(c, a, b) \
    asm volatile("mma.sync.aligned.m16n8k16.row.col.f32.bf16.bf16.f32 " \
        "{%0,%1,%2,%3}, {%4,%5,%6,%7}, {%8,%9}, {%0,%1,%2,%3};" \
        : "+f"((c)[0]), "+f"((c)[1]), "+f"((c)[2]), "+f"((c)[3]) \
        : "r"((a)[0]), "r"((a)[1]), "r"((a)[2]), "r"((a)[3]), "r"((b)[0]), "r"((b)[1]))

// ===========================================================================
// Scratch (__device__ globals; no cudaMalloc allowed)
// ===========================================================================
__device__ float g_Q[(size_t)BATCH * SEQ * DMODEL];
__device__ float g_K[(size_t)BATCH * SEQ * DMODEL];
__device__ float g_V[(size_t)BATCH * SEQ * DMODEL];
__device__ float g_ctx[(size_t)BATCH * SEQ * DMODEL];
__device__ float g_attn[(size_t)BATCH * NHEAD * SEQ * SEQ];
__device__ __nv_bfloat16 g_Ahi[(size_t)BATCH * SEQ * DMODEL];
__device__ __nv_bfloat16 g_Alo[(size_t)BATCH * SEQ * DMODEL];
__device__ __nv_bfloat16 g_Whi[(size_t)DMODEL * DMODEL];
__device__ __nv_bfloat16 g_Wlo[(size_t)DMODEL * DMODEL];

// ===========================================================================
// fp32 -> bf16 hi/lo split
// ===========================================================================
__global__ void __launch_bounds__(256)
split_bf16(const float* __restrict__ x, __nv_bfloat16* __restrict__ hi,
           __nv_bfloat16* __restrict__ lo, int n4)
{
    int i = blockIdx.x * 256 + threadIdx.x;
    if (i >= n4) return;
    float4 v = reinterpret_cast<const float4*>(x)[i];
    __nv_bfloat16 h0 = __float2bfloat16(v.x);
    __nv_bfloat16 h1 = __float2bfloat16(v.y);
    __nv_bfloat16 h2 = __float2bfloat16(v.z);
    __nv_bfloat16 h3 = __float2bfloat16(v.w);
    __nv_bfloat16 l0 = __float2bfloat16(v.x - __bfloat162float(h0));
    __nv_bfloat16 l1 = __float2bfloat16(v.y - __bfloat162float(h1));
    __nv_bfloat16 l2 = __float2bfloat16(v.z - __bfloat162float(h2));
    __nv_bfloat16 l3 = __float2bfloat16(v.w - __bfloat162float(h3));
    __nv_bfloat162* hp = reinterpret_cast<__nv_bfloat162*>(hi);
    __nv_bfloat162* lp = reinterpret_cast<__nv_bfloat162*>(lo);
    hp[2 * i]     = __nv_bfloat162(h0, h1);
    hp[2 * i + 1] = __nv_bfloat162(h2, h3);
    lp[2 * i]     = __nv_bfloat162(l0, l1);
    lp[2 * i + 1] = __nv_bfloat162(l2, l3);
}

// ===========================================================================
// HMMA GEMM: C[M,N] = A[M,K] @ W[N,K]^T + bias  (bf16x3 split, fp32 accum)
// CTA tile 128x128, 8 warps (4M x 2N), warp tile 32x64, BK=16, 2-stage cp.async.
// smem: 2 stages x 4 tiles (Ahi,Alo,Bhi,Blo) x 128 rows x 24 bf16 = 49152 B.
// ===========================================================================
#define GK 1024
#define NKSTEP (GK / 16)   // 64

__global__ void __launch_bounds__(256)
gemm_bf16x3_mma(const __nv_bfloat16* __restrict__ Ahi, const __nv_bfloat16* __restrict__ Alo,
                const __nv_bfloat16* __restrict__ Bhi, const __nv_bfloat16* __restrict__ Blo,
                const float* __restrict__ bias, float* __restrict__ C, int N)
{
    __shared__ __align__(128) __nv_bfloat16 smem_t[2][4][128 * 24];

    const int tid  = threadIdx.x;
    const int lane = tid & 31;
    const int wid  = tid >> 5;
    const int wm   = wid & 3;        // 0..3 -> M offset wm*32
    const int wn   = wid >> 2;       // 0..1 -> N offset wn*64
    const int mBase = blockIdx.y * 128;
    const int nBase = blockIdx.x * 128;

    const uint32_t su32 = smem_to_u32(smem_t);

    float c[2][8][4];
#pragma unroll
    for (int mf = 0; mf < 2; mf++)
#pragma unroll
        for (int nf = 0; nf < 8; nf++)
#pragma unroll
            for (int j = 0; j < 4; j++) c[mf][nf][j] = 0.f;

    // loader mapping: thread t loads 16B (8 bf16) per tile per chunk
    const int lr = tid >> 1;             // row 0..127
    const int lh = (tid & 1) * 8;        // k offset 0 or 8
    const __nv_bfloat16* gp0 = Ahi + (size_t)(mBase + lr) * GK + lh;
    const __nv_bfloat16* gp1 = Alo + (size_t)(mBase + lr) * GK + lh;
    const __nv_bfloat16* gp2 = Bhi + (size_t)(nBase + lr) * GK + lh;
    const __nv_bfloat16* gp3 = Blo + (size_t)(nBase + lr) * GK + lh;
    const uint32_t soff = (uint32_t)(lr * 24 + lh) * 2;

    auto load_chunk = [&](int st, int kc) {
        uint32_t base = su32 + (uint32_t)st * 4 * 6144 + soff;
        const int ko = kc * 16;
        cp_async16(base,            gp0 + ko);
        cp_async16(base + 6144,     gp1 + ko);
        cp_async16(base + 2 * 6144, gp2 + ko);
        cp_async16(base + 3 * 6144, gp3 + ko);
    };

    load_chunk(0, 0);
    cp_commit();

    const int lrow = lane & 15;          // ldmatrix row select
    const int lcol = (lane >> 4) * 8;    // ldmatrix k half

    for (int i = 0; i < NKSTEP; i++) {
        const int s = i & 1;
        if (i + 1 < NKSTEP) {
            load_chunk(s ^ 1, i + 1);
            cp_commit();
            cp_wait1();
        } else {
            cp_wait0();
        }
        __syncthreads();

        const uint32_t sb = su32 + (uint32_t)s * 4 * 6144;

        // B fragments: 8 n-frags (n8 each), hi + lo
        uint32_t bh[8][2], bl[8][2];
#pragma unroll
        for (int nf4 = 0; nf4 < 4; nf4++) {
            uint32_t addr = sb + 2 * 6144 +
                (uint32_t)((wn * 64 + nf4 * 16 + lrow) * 24 + lcol) * 2;
            LDSM_X4(bh[nf4 * 2][0], bh[nf4 * 2 + 1][0],
                    bh[nf4 * 2][1], bh[nf4 * 2 + 1][1], addr);
            LDSM_X4(bl[nf4 * 2][0], bl[nf4 * 2 + 1][0],
                    bl[nf4 * 2][1], bl[nf4 * 2 + 1][1], addr + 6144);
        }

#pragma unroll
        for (int mf = 0; mf < 2; mf++) {
            uint32_t aaddr = sb + (uint32_t)((wm * 32 + mf * 16 + lrow) * 24 + lcol) * 2;
            uint32_t ah[4], al[4];
            LDSM_X4(ah[0], ah[1], ah[2], ah[3], aaddr);
            LDSM_X4(al[0], al[1], al[2], al[3], aaddr + 6144);
#pragma unroll
            for (int nf = 0; nf < 8; nf++) {
                MMA16816(c[mf][nf], ah, bh[nf]);
                MMA16816(c[mf][nf], ah, bl[nf]);
                MMA16816(c[mf][nf], al, bh[nf]);
            }
        }
        __syncthreads();
    }

    // epilogue
#pragma unroll
    for (int mf = 0; mf < 2; mf++) {
        const int row0 = mBase + wm * 32 + mf * 16 + (lane >> 2);
#pragma unroll
        for (int nf = 0; nf < 8; nf++) {
            const int col = nBase + wn * 64 + nf * 8 + (lane & 3) * 2;
            const float b0 = bias[col], b1 = bias[col + 1];
            float2 v0 = make_float2(c[mf][nf][0] + b0, c[mf][nf][1] + b1);
            float2 v1 = make_float2(c[mf][nf][2] + b0, c[mf][nf][3] + b1);
            *reinterpret_cast<float2*>(C + (size_t)row0 * N + col)       = v0;
            *reinterpret_cast<float2*>(C + (size_t)(row0 + 8) * N + col) = v1;
        }
    }
}

// ===========================================================================
// scores[b,h,s,t] = QK^T/8 + rel_bias, causal-masked. 64x64 tiles.
// ===========================================================================
__global__ void __launch_bounds__(256)
scores_kernel(const float* __restrict__ rel_bias)
{
    const int bh = blockIdx.z;
    const int b  = bh >> 4;
    const int h  = bh & 15;
    const int s0 = blockIdx.y * 64;
    const int t0 = blockIdx.x * 64;
    if (t0 > s0 + 63) return;

    __shared__ float Qs[64][68];
    __shared__ float Ks[64][68];

    const int tid = threadIdx.x;
    const float* Qb = g_Q + ((size_t)b * SEQ + s0) * DMODEL + h * DK;
    const float* Kb = g_K + ((size_t)b * SEQ + t0) * DMODEL + h * DK;

#pragma unroll
    for (int i = 0; i < 4; i++) {
        int f  = tid + i * 256;
        int r  = f >> 4;
        int dg = (f & 15) * 4;
        float4 q = *reinterpret_cast<const float4*>(Qb + (size_t)r * DMODEL + dg);
        Qs[dg + 0][r] = q.x; Qs[dg + 1][r] = q.y;
        Qs[dg + 2][r] = q.z; Qs[dg + 3][r] = q.w;
        float4 kv = *reinterpret_cast<const float4*>(Kb + (size_t)r * DMODEL + dg);
        Ks[dg + 0][r] = kv.x; Ks[dg + 1][r] = kv.y;
        Ks[dg + 2][r] = kv.z; Ks[dg + 3][r] = kv.w;
    }
    __syncthreads();

    const int tx = tid & 15;
    const int ty = tid >> 4;
    float acc[4][4];
#pragma unroll
    for (int m = 0; m < 4; m++)
#pragma unroll
        for (int n = 0; n < 4; n++) acc[m][n] = 0.f;

#pragma unroll
    for (int d = 0; d < 64; d++) {
        float4 rq = *reinterpret_cast<const float4*>(&Qs[d][ty * 4]);
        float4 rk = *reinterpret_cast<const float4*>(&Ks[d][tx * 4]);
        float ra[4] = {rq.x, rq.y, rq.z, rq.w};
        float rb[4] = {rk.x, rk.y, rk.z, rk.w};
#pragma unroll
        for (int m = 0; m < 4; m++)
#pragma unroll
            for (int n = 0; n < 4; n++)
                acc[m][n] = fmaf(ra[m], rb[n], acc[m][n]);
    }

    const float inv_scale = 0.125f;
    float* arow = g_attn + ((size_t)bh * SEQ) * SEQ;
#pragma unroll
    for (int m = 0; m < 4; m++) {
        int s = s0 + ty * 4 + m;
        const float* rb_ptr = rel_bias + ((size_t)h * SEQ + s) * SEQ;
        float* wr = arow + (size_t)s * SEQ;
#pragma unroll
        for (int n = 0; n < 4; n++) {
            int t = t0 + tx * 4 + n;
            float v = (t <= s) ? (acc[m][n] * inv_scale + rb_ptr[t]) : -INFINITY;
            wr[t] = v;
        }
    }
}

// ===========================================================================
// Row softmax, in place; zeros above diagonal.
// ===========================================================================
__device__ __forceinline__ float warpMaxf(float v) {
#pragma unroll
    for (int o = 16; o; o >>= 1) v = fmaxf(v, __shfl_xor_sync(0xffffffffu, v, o));
    return v;
}
__device__ __forceinline__ float warpSumf(float v) {
#pragma unroll
    for (int o = 16; o; o >>= 1) v += __shfl_xor_sync(0xffffffffu, v, o);
    return v;
}

__global__ void __launch_bounds__(256)
softmax_kernel()
{
    const int s  = blockIdx.x;
    const int bh = blockIdx.y;
    float* row = g_attn + ((size_t)bh * SEQ + s) * SEQ;
    const int tid = threadIdx.x;
    const int L = s + 1;

    __shared__ float red[8];

    int t0 = tid, t1 = tid + 256;
    float v0 = (t0 < L) ? row[t0] : -INFINITY;
    float v1 = (t1 < L) ? row[t1] : -INFINITY;

    float mx = warpMaxf(fmaxf(v0, v1));
    if ((tid & 31) == 0) red[tid >> 5] = mx;
    __syncthreads();
    if (tid < 8) { float t = red[tid]; t = fmaxf(t, __shfl_xor_sync(0xffu, t, 4));
                   t = fmaxf(t, __shfl_xor_sync(0xffu, t, 2));
                   t = fmaxf(t, __shfl_xor_sync(0xffu, t, 1)); red[tid] = t; }
    __syncthreads();
    mx = red[0];

    float e0 = (t0 < L) ? __expf(v0 - mx) : 0.f;
    float e1 = (t1 < L) ? __expf(v1 - mx) : 0.f;
    float sm = warpSumf(e0 + e1);
    __syncthreads();
    if ((tid & 31) == 0) red[tid >> 5] = sm;
    __syncthreads();
    if (tid < 8) { float t = red[tid]; t += __shfl_xor_sync(0xffu, t, 4);
                   t += __shfl_xor_sync(0xffu, t, 2);
                   t += __shfl_xor_sync(0xffu, t, 1); red[tid] = t; }
    __syncthreads();
    float inv = 1.f / red[0];

    row[t0] = e0 * inv;
    row[t1] = e1 * inv;
}

// ===========================================================================
// attn head-mean
// ===========================================================================
__global__ void __launch_bounds__(256)
mean_kernel(float* __restrict__ out2)
{
    const size_t idx = (size_t)blockIdx.x * 256 + threadIdx.x;
    const size_t SS = (size_t)SEQ * SEQ;
    const int b = (int)(idx / SS);
    const size_t r = idx % SS;
    const float* base = g_attn + (size_t)b * NHEAD * SS + r;
    float sum = 0.f;
#pragma unroll
    for (int h = 0; h < NHEAD; h++) sum += base[(size_t)h * SS];
    out2[idx] = sum * (1.f / NHEAD);
}

// ===========================================================================
// ctx[b,s,h,d] = sum_t attn[b,h,s,t] * V[b,t,h,d]
// ===========================================================================
__global__ void __launch_bounds__(256)
ctx_kernel()
{
    const int bh = blockIdx.z;
    const int b  = bh >> 4;
    const int h  = bh & 15;
    const int s0 = blockIdx.y * 64;

    __shared__ float As[16][68];
    __shared__ float Bs[16][68];

    const int tid = threadIdx.x;
    const int tx = tid & 15;
    const int ty = tid >> 4;

    const float* Arow = g_attn + ((size_t)bh * SEQ) * SEQ;
    const float* Vb   = g_V + (size_t)b * SEQ * DMODEL + h * DK;

    float acc[4][4];
#pragma unroll
    for (int m = 0; m < 4; m++)
#pragma unroll
        for (int n = 0; n < 4; n++) acc[m][n] = 0.f;

    const int kmax = s0 + 64;
    const int ar = tid >> 2;
    const int ak = (tid & 3) * 4;
    const int vr = tid >> 4;
    const int vc = (tid & 15) * 4;

    for (int k0 = 0; k0 < kmax; k0 += 16) {
        float4 av = *reinterpret_cast<const float4*>(Arow + (size_t)(s0 + ar) * SEQ + k0 + ak);
        As[ak + 0][ar] = av.x; As[ak + 1][ar] = av.y;
        As[ak + 2][ar] = av.z; As[ak + 3][ar] = av.w;
        float4 vv = *reinterpret_cast<const float4*>(Vb + (size_t)(k0 + vr) * DMODEL + vc);
        Bs[vr][vc + 0] = vv.x; Bs[vr][vc + 1] = vv.y;
        Bs[vr][vc + 2] = vv.z; Bs[vr][vc + 3] = vv.w;
        __syncthreads();

#pragma unroll
        for (int kk = 0; kk < 16; kk++) {
            float4 ra4 = *reinterpret_cast<const float4*>(&As[kk][ty * 4]);
            float4 rb4 = *reinterpret_cast<const float4*>(&Bs[kk][tx * 4]);
            float ra[4] = {ra4.x, ra4.y, ra4.z, ra4.w};
            float rb[4] = {rb4.x, rb4.y, rb4.z, rb4.w};
#pragma unroll
            for (int m = 0; m < 4; m++)
#pragma unroll
                for (int n = 0; n < 4; n++)
                    acc[m][n] = fmaf(ra[m], rb[n], acc[m][n]);
        }
        __syncthreads();
    }

#pragma unroll
    for (int m = 0; m < 4; m++) {
        int s = s0 + ty * 4 + m;
        float* cp = g_ctx + ((size_t)b * SEQ + s) * DMODEL + h * DK + tx * 4;
        float4 o = make_float4(acc[m][0], acc[m][1], acc[m][2], acc[m][3]);
        *reinterpret_cast<float4*>(cp) = o;
    }
}

// ===========================================================================
// Launch
// ===========================================================================
extern "C" void kernel_launch(void* const* d_in, const int* in_sizes, int n_in,
                              void* d_out, int out_size)
{
    const float* query = (const float*)d_in[0];
    const float* key   = (const float*)d_in[1];
    const float* value = (const float*)d_in[2];
    const float* wq_w  = (const float*)d_in[3];
    const float* wq_b  = (const float*)d_in[4];
    const float* wk_w  = (const float*)d_in[5];
    const float* wk_b  = (const float*)d_in[6];
    const float* wv_w  = (const float*)d_in[7];
    const float* wv_b  = (const float*)d_in[8];
    const float* wo_w  = (const float*)d_in[9];
    const float* wo_b  = (const float*)d_in[10];
    const float* rel_bias = (const float*)d_in[11];

    float* out  = (float*)d_out;
    const size_t out1_elems = (size_t)BATCH * SEQ * DMODEL;
    const size_t out2_elems = (size_t)BATCH * SEQ * SEQ;
    float* out2 = out + out1_elems;

    float *qP, *kP, *vP, *cP;
    cudaGetSymbolAddress((void**)&qP, g_Q);
    cudaGetSymbolAddress((void**)&kP, g_K);
    cudaGetSymbolAddress((void**)&vP, g_V);
    cudaGetSymbolAddress((void**)&cP, g_ctx);
    __nv_bfloat16 *ahi, *alo, *whi, *wlo;
    cudaGetSymbolAddress((void**)&ahi, g_Ahi);
    cudaGetSymbolAddress((void**)&alo, g_Alo);
    cudaGetSymbolAddress((void**)&whi, g_Whi);
    cudaGetSymbolAddress((void**)&wlo, g_Wlo);

    const int M = BATCH * SEQ;   // 8192
    const int N = DMODEL;        // 1024
    const int nA4 = M * DMODEL / 4;
    const int nW4 = N * DMODEL / 4;
    dim3 gG(N / 128, M / 128);   // (8, 64)

    // Q projection
    split_bf16<<<nA4 / 256, 256>>>(query, ahi, alo, nA4);
    split_bf16<<<nW4 / 256, 256>>>(wq_w, whi, wlo, nW4);
    gemm_bf16x3_mma<<<gG, 256>>>(ahi, alo, whi, wlo, wq_b, qP, N);
    // K projection
    split_bf16<<<nA4 / 256, 256>>>(key, ahi, alo, nA4);
    split_bf16<<<nW4 / 256, 256>>>(wk_w, whi, wlo, nW4);
    gemm_bf16x3_mma<<<gG, 256>>>(ahi, alo, whi, wlo, wk_b, kP, N);
    // V projection
    split_bf16<<<nA4 / 256, 256>>>(value, ahi, alo, nA4);
    split_bf16<<<nW4 / 256, 256>>>(wv_w, whi, wlo, nW4);
    gemm_bf16x3_mma<<<gG, 256>>>(ahi, alo, whi, wlo, wv_b, vP, N);

    // attention
    scores_kernel<<<dim3(SEQ / 64, SEQ / 64, BATCH * NHEAD), 256>>>(rel_bias);
    softmax_kernel<<<dim3(SEQ, BATCH * NHEAD), 256>>>();

    if ((size_t)out_size >= out1_elems + out2_elems) {
        mean_kernel<<<(unsigned)(out2_elems / 256), 256>>>(out2);
    }

    ctx_kernel<<<dim3(1, SEQ / 64, BATCH * NHEAD), 256>>>();

    // output projection
    split_bf16<<<nA4 / 256, 256>>>(cP, ahi, alo, nA4);
    split_bf16<<<nW4 / 256, 256>>>(wo_w, whi, wlo, nW4);
    gemm_bf16x3_mma<<<gG, 256>>>(ahi, alo, whi, wlo, wo_b, out, N);
}

// round 4
// speedup vs baseline: 1.7982x; 1.1337x over previous
#include <cuda_runtime.h>
#include <cuda_bf16.h>
#include <cstdint>
#include <math.h>

#define BATCH 16
#define SEQ   512
#define DMODEL 1024
#define NHEAD 16
#define DK    64
#define BH    (BATCH * NHEAD)

// ===========================================================================
// Portable PTX helpers
// ===========================================================================
__device__ __forceinline__ uint32_t smem_to_u32(const void* p) {
    uint32_t a;
    asm("{ .reg .u64 t; cvta.to.shared.u64 t, %1; cvt.u32.u64 %0, t; }" : "=r"(a) : "l"(p));
    return a;
}
__device__ __forceinline__ void cp_async16(uint32_t smem_addr, const void* gptr) {
    asm volatile("cp.async.cg.shared.global [%0], [%1], 16;" :: "r"(smem_addr), "l"(gptr) : "memory");
}
__device__ __forceinline__ void cp_commit() { asm volatile("cp.async.commit_group;" ::: "memory"); }
__device__ __forceinline__ void cp_wait1()  { asm volatile("cp.async.wait_group 1;" ::: "memory"); }
__device__ __forceinline__ void cp_wait0()  { asm volatile("cp.async.wait_group 0;" ::: "memory"); }

#define LDSM_X4(r0, r1, r2, r3, addr) \
    asm volatile("ldmatrix.sync.aligned.m8n8.x4.shared.b16 {%0,%1,%2,%3}, [%4];" \
        : "=r"(r0), "=r"(r1), "=r"(r2), "=r"(r3) : "r"(addr))

#define LDSM_X4_T(r0, r1, r2, r3, addr) \
    asm volatile("ldmatrix.sync.aligned.m8n8.x4.trans.shared.b16 {%0,%1,%2,%3}, [%4];" \
        : "=r"(r0), "=r"(r1), "=r"(r2), "=r"(r3) : "r"(addr))

#define MMA16816(c, a, b) \
    asm volatile("mma.sync.aligned.m16n8k16.row.col.f32.bf16.bf16.f32 " \
        "{%0,%1,%2,%3}, {%4,%5,%6,%7}, {%8,%9}, {%0,%1,%2,%3};" \
        : "+f"((c)[0]), "+f"((c)[1]), "+f"((c)[2]), "+f"((c)[3]) \
        : "r"((a)[0]), "r"((a)[1]), "r"((a)[2]), "r"((a)[3]), "r"((b)[0]), "r"((b)[1]))

// ===========================================================================
// Scratch (__device__ globals)
// ===========================================================================
__device__ __nv_bfloat16 g_Ahi[(size_t)BATCH * SEQ * DMODEL];
__device__ __nv_bfloat16 g_Alo[(size_t)BATCH * SEQ * DMODEL];
__device__ __nv_bfloat16 g_Whi[(size_t)DMODEL * DMODEL];
__device__ __nv_bfloat16 g_Wlo[(size_t)DMODEL * DMODEL];
__device__ __nv_bfloat16 g_Qh[(size_t)BATCH * SEQ * DMODEL];
__device__ __nv_bfloat16 g_Ql[(size_t)BATCH * SEQ * DMODEL];
__device__ __nv_bfloat16 g_Kh[(size_t)BATCH * SEQ * DMODEL];
__device__ __nv_bfloat16 g_Kl[(size_t)BATCH * SEQ * DMODEL];
__device__ __nv_bfloat16 g_Vh[(size_t)BATCH * SEQ * DMODEL];
__device__ __nv_bfloat16 g_Vl[(size_t)BATCH * SEQ * DMODEL];
__device__ __nv_bfloat16 g_Ch[(size_t)BATCH * SEQ * DMODEL];
__device__ __nv_bfloat16 g_Cl[(size_t)BATCH * SEQ * DMODEL];
__device__ __nv_bfloat16 g_Ph[(size_t)BH * SEQ * SEQ];
__device__ __nv_bfloat16 g_Pl[(size_t)BH * SEQ * SEQ];

// ===========================================================================
// fp32 -> bf16 hi/lo split
// ===========================================================================
__global__ void __launch_bounds__(256)
split_bf16(const float* __restrict__ x, __nv_bfloat16* __restrict__ hi,
           __nv_bfloat16* __restrict__ lo, int n4)
{
    int i = blockIdx.x * 256 + threadIdx.x;
    if (i >= n4) return;
    float4 v = reinterpret_cast<const float4*>(x)[i];
    __nv_bfloat16 h0 = __float2bfloat16(v.x);
    __nv_bfloat16 h1 = __float2bfloat16(v.y);
    __nv_bfloat16 h2 = __float2bfloat16(v.z);
    __nv_bfloat16 h3 = __float2bfloat16(v.w);
    __nv_bfloat16 l0 = __float2bfloat16(v.x - __bfloat162float(h0));
    __nv_bfloat16 l1 = __float2bfloat16(v.y - __bfloat162float(h1));
    __nv_bfloat16 l2 = __float2bfloat16(v.z - __bfloat162float(h2));
    __nv_bfloat16 l3 = __float2bfloat16(v.w - __bfloat162float(h3));
    __nv_bfloat162* hp = reinterpret_cast<__nv_bfloat162*>(hi);
    __nv_bfloat162* lp = reinterpret_cast<__nv_bfloat162*>(lo);
    hp[2 * i]     = __nv_bfloat162(h0, h1);
    hp[2 * i + 1] = __nv_bfloat162(h2, h3);
    lp[2 * i]     = __nv_bfloat162(l0, l1);
    lp[2 * i + 1] = __nv_bfloat162(l2, l3);
}

// ===========================================================================
// HMMA GEMM: C = A @ W^T + bias  (bf16x3). Epilogue: fp32 OR bf16 hi/lo out.
// ===========================================================================
#define GK 1024
#define NKSTEP (GK / 16)

__global__ void __launch_bounds__(256)
gemm_bf16x3_mma(const __nv_bfloat16* __restrict__ Ahi, const __nv_bfloat16* __restrict__ Alo,
                const __nv_bfloat16* __restrict__ Bhi, const __nv_bfloat16* __restrict__ Blo,
                const float* __restrict__ bias, float* __restrict__ C,
                __nv_bfloat16* __restrict__ Chi, __nv_bfloat16* __restrict__ Clo, int N)
{
    __shared__ __align__(128) __nv_bfloat16 smem_t[2][4][128 * 24];

    const int tid  = threadIdx.x;
    const int lane = tid & 31;
    const int wid  = tid >> 5;
    const int wm   = wid & 3;
    const int wn   = wid >> 2;
    const int mBase = blockIdx.y * 128;
    const int nBase = blockIdx.x * 128;

    const uint32_t su32 = smem_to_u32(smem_t);

    float c[2][8][4];
#pragma unroll
    for (int mf = 0; mf < 2; mf++)
#pragma unroll
        for (int nf = 0; nf < 8; nf++)
#pragma unroll
            for (int j = 0; j < 4; j++) c[mf][nf][j] = 0.f;

    const int lr = tid >> 1;
    const int lh = (tid & 1) * 8;
    const __nv_bfloat16* gp0 = Ahi + (size_t)(mBase + lr) * GK + lh;
    const __nv_bfloat16* gp1 = Alo + (size_t)(mBase + lr) * GK + lh;
    const __nv_bfloat16* gp2 = Bhi + (size_t)(nBase + lr) * GK + lh;
    const __nv_bfloat16* gp3 = Blo + (size_t)(nBase + lr) * GK + lh;
    const uint32_t soff = (uint32_t)(lr * 24 + lh) * 2;

    auto load_chunk = [&](int st, int kc) {
        uint32_t base = su32 + (uint32_t)st * 4 * 6144 + soff;
        const int ko = kc * 16;
        cp_async16(base,            gp0 + ko);
        cp_async16(base + 6144,     gp1 + ko);
        cp_async16(base + 2 * 6144, gp2 + ko);
        cp_async16(base + 3 * 6144, gp3 + ko);
    };

    load_chunk(0, 0);
    cp_commit();

    const int lrow = lane & 15;
    const int lcol = (lane >> 4) * 8;

    for (int i = 0; i < NKSTEP; i++) {
        const int s = i & 1;
        if (i + 1 < NKSTEP) {
            load_chunk(s ^ 1, i + 1);
            cp_commit();
            cp_wait1();
        } else {
            cp_wait0();
        }
        __syncthreads();

        const uint32_t sb = su32 + (uint32_t)s * 4 * 6144;

        uint32_t bh[8][2], bl[8][2];
#pragma unroll
        for (int nf4 = 0; nf4 < 4; nf4++) {
            uint32_t addr = sb + 2 * 6144 +
                (uint32_t)((wn * 64 + nf4 * 16 + lrow) * 24 + lcol) * 2;
            LDSM_X4(bh[nf4 * 2][0], bh[nf4 * 2 + 1][0],
                    bh[nf4 * 2][1], bh[nf4 * 2 + 1][1], addr);
            LDSM_X4(bl[nf4 * 2][0], bl[nf4 * 2 + 1][0],
                    bl[nf4 * 2][1], bl[nf4 * 2 + 1][1], addr + 6144);
        }

#pragma unroll
        for (int mf = 0; mf < 2; mf++) {
            uint32_t aaddr = sb + (uint32_t)((wm * 32 + mf * 16 + lrow) * 24 + lcol) * 2;
            uint32_t ah[4], al[4];
            LDSM_X4(ah[0], ah[1], ah[2], ah[3], aaddr);
            LDSM_X4(al[0], al[1], al[2], al[3], aaddr + 6144);
#pragma unroll
            for (int nf = 0; nf < 8; nf++) {
                MMA16816(c[mf][nf], ah, bh[nf]);
                MMA16816(c[mf][nf], ah, bl[nf]);
                MMA16816(c[mf][nf], al, bh[nf]);
            }
        }
        __syncthreads();
    }

#pragma unroll
    for (int mf = 0; mf < 2; mf++) {
        const int row0 = mBase + wm * 32 + mf * 16 + (lane >> 2);
#pragma unroll
        for (int nf = 0; nf < 8; nf++) {
            const int col = nBase + wn * 64 + nf * 8 + (lane & 3) * 2;
            const float b0 = bias[col], b1 = bias[col + 1];
            float v00 = c[mf][nf][0] + b0, v01 = c[mf][nf][1] + b1;
            float v10 = c[mf][nf][2] + b0, v11 = c[mf][nf][3] + b1;
            if (Chi) {
                __nv_bfloat16 h00 = __float2bfloat16(v00), h01 = __float2bfloat16(v01);
                __nv_bfloat16 h10 = __float2bfloat16(v10), h11 = __float2bfloat16(v11);
                size_t o0 = (size_t)row0 * N + col, o1 = (size_t)(row0 + 8) * N + col;
                *reinterpret_cast<__nv_bfloat162*>(Chi + o0) = __nv_bfloat162(h00, h01);
                *reinterpret_cast<__nv_bfloat162*>(Chi + o1) = __nv_bfloat162(h10, h11);
                *reinterpret_cast<__nv_bfloat162*>(Clo + o0) = __nv_bfloat162(
                    __float2bfloat16(v00 - __bfloat162float(h00)),
                    __float2bfloat16(v01 - __bfloat162float(h01)));
                *reinterpret_cast<__nv_bfloat162*>(Clo + o1) = __nv_bfloat162(
                    __float2bfloat16(v10 - __bfloat162float(h10)),
                    __float2bfloat16(v11 - __bfloat162float(h11)));
            } else {
                *reinterpret_cast<float2*>(C + (size_t)row0 * N + col)       = make_float2(v00, v01);
                *reinterpret_cast<float2*>(C + (size_t)(row0 + 8) * N + col) = make_float2(v10, v11);
            }
        }
    }
}

// ===========================================================================
// Fused scores (HMMA bf16x3) + softmax. One CTA per (bh, 64 s-rows).
// Writes probs as bf16 hi/lo to g_Ph/g_Pl (cols [0, s0+64) only).
// ===========================================================================
#define S_STRIDE 516
#define FS_SBYTES (64 * S_STRIDE * 4)          // 132096
#define FS_TSTRIDE 72
#define FS_TILE (64 * FS_TSTRIDE)              // elems per tile buffer
#define FS_SMEM (FS_SBYTES + 4 * FS_TILE * 2)  // 168960

__global__ void __launch_bounds__(256)
fused_scores_softmax(const float* __restrict__ rel_bias)
{
    extern __shared__ __align__(128) char fsmem[];
    float* S = reinterpret_cast<float*>(fsmem);
    __nv_bfloat16* tQh = reinterpret_cast<__nv_bfloat16*>(fsmem + FS_SBYTES);
    __nv_bfloat16* tQl = tQh + FS_TILE;
    __nv_bfloat16* tKh = tQl + FS_TILE;
    __nv_bfloat16* tKl = tKh + FS_TILE;

    const int s0 = blockIdx.x * 64;
    const int bh = blockIdx.y;
    const int b  = bh >> 4;
    const int h  = bh & 15;
    const int tid = threadIdx.x, lane = tid & 31, wid = tid >> 5;
    const int wm = wid & 3, wn = wid >> 2;

    const uint32_t uQh = smem_to_u32(tQh);
    const uint32_t uQl = smem_to_u32(tQl);
    const uint32_t uKh = smem_to_u32(tKh);
    const uint32_t uKl = smem_to_u32(tKl);

    // loaders: 4 threads/row, each 2x16B -> 128B row
    const int lr = tid >> 2;
    const int cb0 = (tid & 3) * 16;
    const char* gQh = (const char*)(g_Qh + ((size_t)(b * SEQ + s0 + lr)) * DMODEL + h * DK);
    const char* gQl = (const char*)(g_Ql + ((size_t)(b * SEQ + s0 + lr)) * DMODEL + h * DK);

#pragma unroll
    for (int j = 0; j < 2; j++) {
        int cb = cb0 + j * 64;
        cp_async16(uQh + lr * 144 + cb, gQh + cb);
        cp_async16(uQl + lr * 144 + cb, gQl + cb);
    }

    const int ntiles = s0 / 64 + 1;

    // preload K tile 0
    {
        const char* gKh = (const char*)(g_Kh + ((size_t)(b * SEQ + lr)) * DMODEL + h * DK);
        const char* gKl = (const char*)(g_Kl + ((size_t)(b * SEQ + lr)) * DMODEL + h * DK);
#pragma unroll
        for (int j = 0; j < 2; j++) {
            int cb = cb0 + j * 64;
            cp_async16(uKh + lr * 144 + cb, gKh + cb);
            cp_async16(uKl + lr * 144 + cb, gKl + cb);
        }
    }
    cp_commit();

    const int lrow = lane & 15;
    const int lcol = (lane >> 4) * 8;

    for (int t = 0; t < ntiles; t++) {
        const int t0 = t * 64;
        cp_wait0();
        __syncthreads();

        float c[4][4];
#pragma unroll
        for (int nf = 0; nf < 4; nf++)
#pragma unroll
            for (int j = 0; j < 4; j++) c[nf][j] = 0.f;

#pragma unroll
        for (int k0 = 0; k0 < 64; k0 += 16) {
            uint32_t aaddr_off = (uint32_t)((wm * 16 + lrow) * FS_TSTRIDE + k0 + lcol) * 2;
            uint32_t ah[4], al[4];
            LDSM_X4(ah[0], ah[1], ah[2], ah[3], uQh + aaddr_off);
            LDSM_X4(al[0], al[1], al[2], al[3], uQl + aaddr_off);
            uint32_t bhf[4][2], blf[4][2];
#pragma unroll
            for (int g = 0; g < 2; g++) {
                uint32_t baddr_off = (uint32_t)((wn * 32 + g * 16 + lrow) * FS_TSTRIDE + k0 + lcol) * 2;
                LDSM_X4(bhf[g * 2][0], bhf[g * 2 + 1][0],
                        bhf[g * 2][1], bhf[g * 2 + 1][1], uKh + baddr_off);
                LDSM_X4(blf[g * 2][0], blf[g * 2 + 1][0],
                        blf[g * 2][1], blf[g * 2 + 1][1], uKl + baddr_off);
            }
#pragma unroll
            for (int nf = 0; nf < 4; nf++) {
                MMA16816(c[nf], ah, bhf[nf]);
                MMA16816(c[nf], ah, blf[nf]);
                MMA16816(c[nf], al, bhf[nf]);
            }
        }

        // epilogue -> S (scale + rel_bias + causal mask)
        {
            const int r0 = wm * 16 + (lane >> 2);
            const int sg0 = s0 + r0, sg1 = sg0 + 8;
#pragma unroll
            for (int nf = 0; nf < 4; nf++) {
                const int col = wn * 32 + nf * 8 + (lane & 3) * 2;
                const int tg = t0 + col;
                float2 rb0 = *reinterpret_cast<const float2*>(
                    rel_bias + ((size_t)h * SEQ + sg0) * SEQ + tg);
                float2 rb1 = *reinterpret_cast<const float2*>(
                    rel_bias + ((size_t)h * SEQ + sg1) * SEQ + tg);
                float v00 = c[nf][0] * 0.125f + rb0.x; if (tg     > sg0) v00 = -INFINITY;
                float v01 = c[nf][1] * 0.125f + rb0.y; if (tg + 1 > sg0) v01 = -INFINITY;
                float v10 = c[nf][2] * 0.125f + rb1.x; if (tg     > sg1) v10 = -INFINITY;
                float v11 = c[nf][3] * 0.125f + rb1.y; if (tg + 1 > sg1) v11 = -INFINITY;
                *reinterpret_cast<float2*>(&S[r0 * S_STRIDE + tg])       = make_float2(v00, v01);
                *reinterpret_cast<float2*>(&S[(r0 + 8) * S_STRIDE + tg]) = make_float2(v10, v11);
            }
        }
        __syncthreads();

        if (t + 1 < ntiles) {
            const int tn = (t + 1) * 64;
            const char* gKh = (const char*)(g_Kh + ((size_t)(b * SEQ + tn + lr)) * DMODEL + h * DK);
            const char* gKl = (const char*)(g_Kl + ((size_t)(b * SEQ + tn + lr)) * DMODEL + h * DK);
#pragma unroll
            for (int j = 0; j < 2; j++) {
                int cb = cb0 + j * 64;
                cp_async16(uKh + lr * 144 + cb, gKh + cb);
                cp_async16(uKl + lr * 144 + cb, gKl + cb);
            }
            cp_commit();
        }
    }

    __syncthreads();

    // softmax: warp w handles rows w*8 .. w*8+7
    const int Lt = s0 + 64;
    for (int r = wid * 8; r < wid * 8 + 8; r++) {
        const int s = s0 + r;
        const int L = s + 1;
        float* row = S + r * S_STRIDE;

        float m = -INFINITY;
        for (int ci = lane; ci < L; ci += 32) m = fmaxf(m, row[ci]);
#pragma unroll
        for (int o = 16; o; o >>= 1) m = fmaxf(m, __shfl_xor_sync(0xffffffffu, m, o));

        float sum = 0.f;
        for (int ci = lane; ci < L; ci += 32) {
            float e = __expf(row[ci] - m);
            row[ci] = e;
            sum += e;
        }
#pragma unroll
        for (int o = 16; o; o >>= 1) sum += __shfl_xor_sync(0xffffffffu, sum, o);
        const float inv = 1.f / sum;

        __nv_bfloat16* oh = g_Ph + ((size_t)bh * SEQ + s) * SEQ;
        __nv_bfloat16* ol = g_Pl + ((size_t)bh * SEQ + s) * SEQ;
        for (int ci = lane; ci < Lt; ci += 32) {
            float p = (ci < L) ? row[ci] * inv : 0.f;
            __nv_bfloat16 ph = __float2bfloat16(p);
            oh[ci] = ph;
            ol[ci] = __float2bfloat16(p - __bfloat162float(ph));
        }
    }
}

// ===========================================================================
// ctx = P @ V via HMMA bf16x3 (ldmatrix.trans for V). One CTA per (bh, 64 rows).
// Writes ctx as bf16 hi/lo.
// ===========================================================================
__global__ void __launch_bounds__(256)
ctx_mma()
{
    __shared__ __align__(128) __nv_bfloat16 tPh[FS_TILE], tPl[FS_TILE], tVh[FS_TILE], tVl[FS_TILE];

    const int s0 = blockIdx.x * 64;
    const int bh = blockIdx.y;
    const int b  = bh >> 4;
    const int h  = bh & 15;
    const int tid = threadIdx.x, lane = tid & 31, wid = tid >> 5;
    const int wm = wid & 3, wn = wid >> 2;

    const uint32_t uPh = smem_to_u32(tPh);
    const uint32_t uPl = smem_to_u32(tPl);
    const uint32_t uVh = smem_to_u32(tVh);
    const uint32_t uVl = smem_to_u32(tVl);

    const int lr = tid >> 2;
    const int cb0 = (tid & 3) * 16;

    float c[4][4];
#pragma unroll
    for (int nf = 0; nf < 4; nf++)
#pragma unroll
        for (int j = 0; j < 4; j++) c[nf][j] = 0.f;

    const int ntiles = s0 / 64 + 1;

    auto load_tile = [&](int t0) {
        const char* gPh = (const char*)(g_Ph + ((size_t)bh * SEQ + s0 + lr) * SEQ + t0);
        const char* gPl = (const char*)(g_Pl + ((size_t)bh * SEQ + s0 + lr) * SEQ + t0);
        const char* gVh = (const char*)(g_Vh + ((size_t)(b * SEQ + t0 + lr)) * DMODEL + h * DK);
        const char* gVl = (const char*)(g_Vl + ((size_t)(b * SEQ + t0 + lr)) * DMODEL + h * DK);
#pragma unroll
        for (int j = 0; j < 2; j++) {
            int cb = cb0 + j * 64;
            cp_async16(uPh + lr * 144 + cb, gPh + cb);
            cp_async16(uPl + lr * 144 + cb, gPl + cb);
            cp_async16(uVh + lr * 144 + cb, gVh + cb);
            cp_async16(uVl + lr * 144 + cb, gVl + cb);
        }
    };

    load_tile(0);
    cp_commit();

    const int lrow = lane & 15;
    const int lcol = (lane >> 4) * 8;

    for (int t = 0; t < ntiles; t++) {
        cp_wait0();
        __syncthreads();

#pragma unroll
        for (int k0 = 0; k0 < 64; k0 += 16) {
            uint32_t aoff = (uint32_t)((wm * 16 + lrow) * FS_TSTRIDE + k0 + lcol) * 2;
            uint32_t ah[4], al[4];
            LDSM_X4(ah[0], ah[1], ah[2], ah[3], uPh + aoff);
            LDSM_X4(al[0], al[1], al[2], al[3], uPl + aoff);
            uint32_t bhf[4][2], blf[4][2];
#pragma unroll
            for (int g = 0; g < 2; g++) {
                // trans ldmatrix: rows = k (t index), cols = n (d index)
                uint32_t boff = (uint32_t)((k0 + lrow) * FS_TSTRIDE + wn * 32 + g * 16 + lcol) * 2;
                LDSM_X4_T(bhf[g * 2][0], bhf[g * 2][1],
                          bhf[g * 2 + 1][0], bhf[g * 2 + 1][1], uVh + boff);
                LDSM_X4_T(blf[g * 2][0], blf[g * 2][1],
                          blf[g * 2 + 1][0], blf[g * 2 + 1][1], uVl + boff);
            }
#pragma unroll
            for (int nf = 0; nf < 4; nf++) {
                MMA16816(c[nf], ah, bhf[nf]);
                MMA16816(c[nf], ah, blf[nf]);
                MMA16816(c[nf], al, bhf[nf]);
            }
        }
        __syncthreads();

        if (t + 1 < ntiles) {
            load_tile((t + 1) * 64);
            cp_commit();
        }
    }

    // epilogue: write ctx bf16 hi/lo
    const int r0 = wm * 16 + (lane >> 2);
#pragma unroll
    for (int nf = 0; nf < 4; nf++) {
        const int col = wn * 32 + nf * 8 + (lane & 3) * 2;
#pragma unroll
        for (int half = 0; half < 2; half++) {
            const int s = s0 + r0 + half * 8;
            const float v0 = c[nf][half * 2], v1 = c[nf][half * 2 + 1];
            __nv_bfloat16 h0 = __float2bfloat16(v0);
            __nv_bfloat16 h1 = __float2bfloat16(v1);
            size_t o = ((size_t)(b * SEQ + s)) * DMODEL + h * DK + col;
            *reinterpret_cast<__nv_bfloat162*>(g_Ch + o) = __nv_bfloat162(h0, h1);
            *reinterpret_cast<__nv_bfloat162*>(g_Cl + o) = __nv_bfloat162(
                __float2bfloat16(v0 - __bfloat162float(h0)),
                __float2bfloat16(v1 - __bfloat162float(h1)));
        }
    }
}

// ===========================================================================
// attn head-mean (causal-bounded; reads hi+lo)
// ===========================================================================
__global__ void __launch_bounds__(256)
mean_kernel(float* __restrict__ out2)
{
    const size_t idx = (size_t)blockIdx.x * 256 + threadIdx.x;
    const int b = (int)(idx >> 18);
    const int r = (int)(idx & 262143);
    const int s = r >> 9;
    const int t = r & 511;
    if (t > s) { out2[idx] = 0.f; return; }
    float sum = 0.f;
#pragma unroll
    for (int h = 0; h < NHEAD; h++) {
        size_t o = ((size_t)(b * NHEAD + h) * SEQ + s) * SEQ + t;
        sum += __bfloat162float(g_Ph[o]) + __bfloat162float(g_Pl[o]);
    }
    out2[idx] = sum * (1.f / NHEAD);
}

// ===========================================================================
// Launch
// ===========================================================================
extern "C" void kernel_launch(void* const* d_in, const int* in_sizes, int n_in,
                              void* d_out, int out_size)
{
    const float* query = (const float*)d_in[0];
    const float* key   = (const float*)d_in[1];
    const float* value = (const float*)d_in[2];
    const float* wq_w  = (const float*)d_in[3];
    const float* wq_b  = (const float*)d_in[4];
    const float* wk_w  = (const float*)d_in[5];
    const float* wk_b  = (const float*)d_in[6];
    const float* wv_w  = (const float*)d_in[7];
    const float* wv_b  = (const float*)d_in[8];
    const float* wo_w  = (const float*)d_in[9];
    const float* wo_b  = (const float*)d_in[10];
    const float* rel_bias = (const float*)d_in[11];

    float* out  = (float*)d_out;
    const size_t out1_elems = (size_t)BATCH * SEQ * DMODEL;
    const size_t out2_elems = (size_t)BATCH * SEQ * SEQ;
    float* out2 = out + out1_elems;

    __nv_bfloat16 *ahi, *alo, *whi, *wlo, *qh, *ql, *kh, *kl, *vh, *vl, *ch, *cl;
    cudaGetSymbolAddress((void**)&ahi, g_Ahi);
    cudaGetSymbolAddress((void**)&alo, g_Alo);
    cudaGetSymbolAddress((void**)&whi, g_Whi);
    cudaGetSymbolAddress((void**)&wlo, g_Wlo);
    cudaGetSymbolAddress((void**)&qh, g_Qh);
    cudaGetSymbolAddress((void**)&ql, g_Ql);
    cudaGetSymbolAddress((void**)&kh, g_Kh);
    cudaGetSymbolAddress((void**)&kl, g_Kl);
    cudaGetSymbolAddress((void**)&vh, g_Vh);
    cudaGetSymbolAddress((void**)&vl, g_Vl);
    cudaGetSymbolAddress((void**)&ch, g_Ch);
    cudaGetSymbolAddress((void**)&cl, g_Cl);

    cudaFuncSetAttribute(fused_scores_softmax,
                         cudaFuncAttributeMaxDynamicSharedMemorySize, FS_SMEM);

    const int M = BATCH * SEQ;
    const int N = DMODEL;
    const int nA4 = M * DMODEL / 4;
    const int nW4 = N * DMODEL / 4;
    dim3 gG(N / 128, M / 128);

    // Q projection -> bf16 hi/lo
    split_bf16<<<nA4 / 256, 256>>>(query, ahi, alo, nA4);
    split_bf16<<<nW4 / 256, 256>>>(wq_w, whi, wlo, nW4);
    gemm_bf16x3_mma<<<gG, 256>>>(ahi, alo, whi, wlo, wq_b, nullptr, qh, ql, N);
    // K projection
    split_bf16<<<nA4 / 256, 256>>>(key, ahi, alo, nA4);
    split_bf16<<<nW4 / 256, 256>>>(wk_w, whi, wlo, nW4);
    gemm_bf16x3_mma<<<gG, 256>>>(ahi, alo, whi, wlo, wk_b, nullptr, kh, kl, N);
    // V projection
    split_bf16<<<nA4 / 256, 256>>>(value, ahi, alo, nA4);
    split_bf16<<<nW4 / 256, 256>>>(wv_w, whi, wlo, nW4);
    gemm_bf16x3_mma<<<gG, 256>>>(ahi, alo, whi, wlo, wv_b, nullptr, vh, vl, N);

    // fused attention scores + softmax (writes prob hi/lo)
    fused_scores_softmax<<<dim3(SEQ / 64, BH), 256, FS_SMEM>>>(rel_bias);

    // head-mean of probs
    if ((size_t)out_size >= out1_elems + out2_elems) {
        mean_kernel<<<(unsigned)(out2_elems / 256), 256>>>(out2);
    }

    // ctx = P @ V  (writes ctx hi/lo)
    ctx_mma<<<dim3(SEQ / 64, BH), 256>>>();

    // output projection (fp32 out)
    split_bf16<<<nW4 / 256, 256>>>(wo_w, whi, wlo, nW4);
    gemm_bf16x3_mma<<<gG, 256>>>(ch, cl, whi, wlo, wo_b, out, nullptr, nullptr, N);
}

// round 5
// speedup vs baseline: 1.8823x; 1.0468x over previous
#include <cuda_runtime.h>
#include <cuda_bf16.h>
#include <cstdint>
#include <math.h>

#define BATCH 16
#define SEQ   512
#define DMODEL 1024
#define NHEAD 16
#define DK    64
#define BH    (BATCH * NHEAD)

// ===========================================================================
// Portable PTX helpers
// ===========================================================================
__device__ __forceinline__ uint32_t smem_to_u32(const void* p) {
    uint32_t a;
    asm("{ .reg .u64 t; cvta.to.shared.u64 t, %1; cvt.u32.u64 %0, t; }" : "=r"(a) : "l"(p));
    return a;
}
__device__ __forceinline__ void cp_async16(uint32_t smem_addr, const void* gptr) {
    asm volatile("cp.async.cg.shared.global [%0], [%1], 16;" :: "r"(smem_addr), "l"(gptr) : "memory");
}
__device__ __forceinline__ void cp_commit() { asm volatile("cp.async.commit_group;" ::: "memory"); }
__device__ __forceinline__ void cp_wait2()  { asm volatile("cp.async.wait_group 2;" ::: "memory"); }
__device__ __forceinline__ void cp_wait0()  { asm volatile("cp.async.wait_group 0;" ::: "memory"); }

#define LDSM_X4(r0, r1, r2, r3, addr) \
    asm volatile("ldmatrix.sync.aligned.m8n8.x4.shared.b16 {%0,%1,%2,%3}, [%4];" \
        : "=r"(r0), "=r"(r1), "=r"(r2), "=r"(r3) : "r"(addr))

#define LDSM_X4_T(r0, r1, r2, r3, addr) \
    asm volatile("ldmatrix.sync.aligned.m8n8.x4.trans.shared.b16 {%0,%1,%2,%3}, [%4];" \
        : "=r"(r0), "=r"(r1), "=r"(r2), "=r"(r3) : "r"(addr))

#define MMA16816(c, a, b) \
    asm volatile("mma.sync.aligned.m16n8k16.row.col.f32.bf16.bf16.f32 " \
        "{%0,%1,%2,%3}, {%4,%5,%6,%7}, {%8,%9}, {%0,%1,%2,%3};" \
        : "+f"((c)[0]), "+f"((c)[1]), "+f"((c)[2]), "+f"((c)[3]) \
        : "r"((a)[0]), "r"((a)[1]), "r"((a)[2]), "r"((a)[3]), "r"((b)[0]), "r"((b)[1]))

// ===========================================================================
// Scratch
// ===========================================================================
#define MTOT (BATCH * SEQ)                      // 8192
__device__ __nv_bfloat16 g_Ahi[(size_t)3 * MTOT * DMODEL];
__device__ __nv_bfloat16 g_Alo[(size_t)3 * MTOT * DMODEL];
__device__ __nv_bfloat16 g_Whi[(size_t)4 * DMODEL * DMODEL];
__device__ __nv_bfloat16 g_Wlo[(size_t)4 * DMODEL * DMODEL];
__device__ __nv_bfloat16 g_Qh[(size_t)MTOT * DMODEL];
__device__ __nv_bfloat16 g_Ql[(size_t)MTOT * DMODEL];
__device__ __nv_bfloat16 g_Kh[(size_t)MTOT * DMODEL];
__device__ __nv_bfloat16 g_Kl[(size_t)MTOT * DMODEL];
__device__ __nv_bfloat16 g_Vh[(size_t)MTOT * DMODEL];
__device__ __nv_bfloat16 g_Vl[(size_t)MTOT * DMODEL];
__device__ __nv_bfloat16 g_Ch[(size_t)MTOT * DMODEL];
__device__ __nv_bfloat16 g_Cl[(size_t)MTOT * DMODEL];
__device__ __nv_bfloat16 g_Ph[(size_t)BH * SEQ * SEQ];
__device__ __nv_bfloat16 g_Pl[(size_t)BH * SEQ * SEQ];

// ===========================================================================
// fp32 -> bf16 hi/lo splits
// ===========================================================================
__device__ __forceinline__ void split_store(const float4 v, __nv_bfloat16* hi,
                                            __nv_bfloat16* lo, size_t i4)
{
    __nv_bfloat16 h0 = __float2bfloat16(v.x);
    __nv_bfloat16 h1 = __float2bfloat16(v.y);
    __nv_bfloat16 h2 = __float2bfloat16(v.z);
    __nv_bfloat16 h3 = __float2bfloat16(v.w);
    __nv_bfloat162* hp = reinterpret_cast<__nv_bfloat162*>(hi);
    __nv_bfloat162* lp = reinterpret_cast<__nv_bfloat162*>(lo);
    hp[2 * i4]     = __nv_bfloat162(h0, h1);
    hp[2 * i4 + 1] = __nv_bfloat162(h2, h3);
    lp[2 * i4]     = __nv_bfloat162(__float2bfloat16(v.x - __bfloat162float(h0)),
                                    __float2bfloat16(v.y - __bfloat162float(h1)));
    lp[2 * i4 + 1] = __nv_bfloat162(__float2bfloat16(v.z - __bfloat162float(h2)),
                                    __float2bfloat16(v.w - __bfloat162float(h3)));
}

__global__ void __launch_bounds__(256)
split_bf16(const float* __restrict__ x, __nv_bfloat16* __restrict__ hi,
           __nv_bfloat16* __restrict__ lo, int n4)
{
    int i = blockIdx.x * 256 + threadIdx.x;
    if (i >= n4) return;
    split_store(reinterpret_cast<const float4*>(x)[i], hi, lo, i);
}

__global__ void __launch_bounds__(256)
split3_bf16(const float* __restrict__ q, const float* __restrict__ k,
            const float* __restrict__ v, __nv_bfloat16* __restrict__ hi,
            __nv_bfloat16* __restrict__ lo, int n4)
{
    int i = blockIdx.x * 256 + threadIdx.x;
    if (i >= n4) return;
    const int z = blockIdx.y;
    const float* src = (z == 0) ? q : ((z == 1) ? k : v);
    split_store(reinterpret_cast<const float4*>(src)[i], hi, lo, (size_t)z * n4 + i);
}

// ===========================================================================
// HMMA GEMM core: C = A @ W^T + bias (bf16x3). 128x128 tile, BK=32,
// 4-stage cp.async pipeline. Epilogue fp32 or bf16 hi/lo.
// smem: 4 stages x 4 tiles x 128 rows x 40 elems x 2B = 163840 B (dynamic).
// ===========================================================================
#define GK 1024
#define NK32 (GK / 32)          // 32 iters
#define T_STRIDE 40             // elems per row (80 B)
#define TILE_B (128 * T_STRIDE * 2)   // 10240
#define STAGE_B (4 * TILE_B)          // 40960
#define GEMM_SMEM (4 * STAGE_B)       // 163840

__device__ __forceinline__ void
gemm_core(const __nv_bfloat16* __restrict__ Ahi, const __nv_bfloat16* __restrict__ Alo,
          const __nv_bfloat16* __restrict__ Bhi, const __nv_bfloat16* __restrict__ Blo,
          const float* __restrict__ bias, float* __restrict__ C,
          __nv_bfloat16* __restrict__ Chi, __nv_bfloat16* __restrict__ Clo,
          char* smem, int mBase, int nBase)
{
    const int tid  = threadIdx.x;
    const int lane = tid & 31;
    const int wid  = tid >> 5;
    const int wm   = wid & 3;
    const int wn   = wid >> 2;
    const uint32_t su32 = smem_to_u32(smem);

    float c[2][8][4];
#pragma unroll
    for (int mf = 0; mf < 2; mf++)
#pragma unroll
        for (int nf = 0; nf < 8; nf++)
#pragma unroll
            for (int j = 0; j < 4; j++) c[mf][nf][j] = 0.f;

    const int lr = tid >> 1;             // row 0..127
    const int lk = (tid & 1) * 16;       // elem 0/16
    const __nv_bfloat16* gp0 = Ahi + (size_t)(mBase + lr) * GK + lk;
    const __nv_bfloat16* gp1 = Alo + (size_t)(mBase + lr) * GK + lk;
    const __nv_bfloat16* gp2 = Bhi + (size_t)(nBase + lr) * GK + lk;
    const __nv_bfloat16* gp3 = Blo + (size_t)(nBase + lr) * GK + lk;
    const uint32_t soff = (uint32_t)(lr * T_STRIDE + lk) * 2;

    auto load_chunk = [&](int st, int kc) {
        uint32_t base = su32 + (uint32_t)st * STAGE_B + soff;
        const int ko = kc * 32;
        cp_async16(base,               gp0 + ko);
        cp_async16(base + 16,          gp0 + ko + 8);
        cp_async16(base + TILE_B,      gp1 + ko);
        cp_async16(base + TILE_B + 16, gp1 + ko + 8);
        cp_async16(base + 2 * TILE_B,      gp2 + ko);
        cp_async16(base + 2 * TILE_B + 16, gp2 + ko + 8);
        cp_async16(base + 3 * TILE_B,      gp3 + ko);
        cp_async16(base + 3 * TILE_B + 16, gp3 + ko + 8);
    };

    load_chunk(0, 0); cp_commit();
    load_chunk(1, 1); cp_commit();
    load_chunk(2, 2); cp_commit();

    const int lrow = lane & 15;
    const int lcol = (lane >> 4) * 8;

    for (int i = 0; i < NK32; i++) {
        cp_wait2();
        __syncthreads();
        if (i + 3 < NK32) load_chunk((i + 3) & 3, i + 3);
        cp_commit();

        const uint32_t sb = su32 + (uint32_t)(i & 3) * STAGE_B;
#pragma unroll
        for (int kh = 0; kh < 32; kh += 16) {
            uint32_t bh[8][2], bl[8][2];
#pragma unroll
            for (int g = 0; g < 4; g++) {
                uint32_t addr = sb + 2 * TILE_B +
                    (uint32_t)((wn * 64 + g * 16 + lrow) * T_STRIDE + kh + lcol) * 2;
                LDSM_X4(bh[g * 2][0], bh[g * 2 + 1][0],
                        bh[g * 2][1], bh[g * 2 + 1][1], addr);
                LDSM_X4(bl[g * 2][0], bl[g * 2 + 1][0],
                        bl[g * 2][1], bl[g * 2 + 1][1], addr + TILE_B);
            }
#pragma unroll
            for (int mf = 0; mf < 2; mf++) {
                uint32_t aaddr = sb +
                    (uint32_t)((wm * 32 + mf * 16 + lrow) * T_STRIDE + kh + lcol) * 2;
                uint32_t ah[4], al[4];
                LDSM_X4(ah[0], ah[1], ah[2], ah[3], aaddr);
                LDSM_X4(al[0], al[1], al[2], al[3], aaddr + TILE_B);
#pragma unroll
                for (int nf = 0; nf < 8; nf++) {
                    MMA16816(c[mf][nf], ah, bh[nf]);
                    MMA16816(c[mf][nf], ah, bl[nf]);
                    MMA16816(c[mf][nf], al, bh[nf]);
                }
            }
        }
    }

#pragma unroll
    for (int mf = 0; mf < 2; mf++) {
        const int row0 = mBase + wm * 32 + mf * 16 + (lane >> 2);
#pragma unroll
        for (int nf = 0; nf < 8; nf++) {
            const int col = nBase + wn * 64 + nf * 8 + (lane & 3) * 2;
            const float b0 = bias[col], b1 = bias[col + 1];
            float v00 = c[mf][nf][0] + b0, v01 = c[mf][nf][1] + b1;
            float v10 = c[mf][nf][2] + b0, v11 = c[mf][nf][3] + b1;
            if (Chi) {
                __nv_bfloat16 h00 = __float2bfloat16(v00), h01 = __float2bfloat16(v01);
                __nv_bfloat16 h10 = __float2bfloat16(v10), h11 = __float2bfloat16(v11);
                size_t o0 = (size_t)row0 * DMODEL + col, o1 = (size_t)(row0 + 8) * DMODEL + col;
                *reinterpret_cast<__nv_bfloat162*>(Chi + o0) = __nv_bfloat162(h00, h01);
                *reinterpret_cast<__nv_bfloat162*>(Chi + o1) = __nv_bfloat162(h10, h11);
                *reinterpret_cast<__nv_bfloat162*>(Clo + o0) = __nv_bfloat162(
                    __float2bfloat16(v00 - __bfloat162float(h00)),
                    __float2bfloat16(v01 - __bfloat162float(h01)));
                *reinterpret_cast<__nv_bfloat162*>(Clo + o1) = __nv_bfloat162(
                    __float2bfloat16(v10 - __bfloat162float(h10)),
                    __float2bfloat16(v11 - __bfloat162float(h11)));
            } else {
                *reinterpret_cast<float2*>(C + (size_t)row0 * DMODEL + col)       = make_float2(v00, v01);
                *reinterpret_cast<float2*>(C + (size_t)(row0 + 8) * DMODEL + col) = make_float2(v10, v11);
            }
        }
    }
}

// Fused Q/K/V projections: blockIdx.z selects projection.
__global__ void __launch_bounds__(256)
gemm_qkv(const __nv_bfloat16* __restrict__ Ahi, const __nv_bfloat16* __restrict__ Alo,
         const __nv_bfloat16* __restrict__ Whi, const __nv_bfloat16* __restrict__ Wlo,
         const float* __restrict__ b0, const float* __restrict__ b1, const float* __restrict__ b2,
         __nv_bfloat16* __restrict__ o0h, __nv_bfloat16* __restrict__ o0l,
         __nv_bfloat16* __restrict__ o1h, __nv_bfloat16* __restrict__ o1l,
         __nv_bfloat16* __restrict__ o2h, __nv_bfloat16* __restrict__ o2l)
{
    extern __shared__ __align__(128) char smem[];
    const int z = blockIdx.z;
    const size_t aoff = (size_t)z * MTOT * GK;
    const size_t woff = (size_t)z * DMODEL * GK;
    const float* bias = (z == 0) ? b0 : ((z == 1) ? b1 : b2);
    __nv_bfloat16* oh = (z == 0) ? o0h : ((z == 1) ? o1h : o2h);
    __nv_bfloat16* ol = (z == 0) ? o0l : ((z == 1) ? o1l : o2l);
    gemm_core(Ahi + aoff, Alo + aoff, Whi + woff, Wlo + woff,
              bias, nullptr, oh, ol, smem, blockIdx.y * 128, blockIdx.x * 128);
}

// Output projection (fp32 out).
__global__ void __launch_bounds__(256)
gemm_out(const __nv_bfloat16* __restrict__ Ahi, const __nv_bfloat16* __restrict__ Alo,
         const __nv_bfloat16* __restrict__ Whi, const __nv_bfloat16* __restrict__ Wlo,
         const float* __restrict__ bias, float* __restrict__ C)
{
    extern __shared__ __align__(128) char smem[];
    gemm_core(Ahi, Alo, Whi, Wlo, bias, C, nullptr, nullptr,
              smem, blockIdx.y * 128, blockIdx.x * 128);
}

// ===========================================================================
// Fused scores (HMMA bf16x3) + softmax. One CTA per (bh, 64 s-rows).
// ===========================================================================
#define S_STRIDE 516
#define FS_SBYTES (64 * S_STRIDE * 4)
#define FS_TSTRIDE 72
#define FS_TILE (64 * FS_TSTRIDE)
#define FS_SMEM (FS_SBYTES + 4 * FS_TILE * 2)

__global__ void __launch_bounds__(256)
fused_scores_softmax(const float* __restrict__ rel_bias)
{
    extern __shared__ __align__(128) char fsmem[];
    float* S = reinterpret_cast<float*>(fsmem);
    __nv_bfloat16* tQh = reinterpret_cast<__nv_bfloat16*>(fsmem + FS_SBYTES);
    __nv_bfloat16* tQl = tQh + FS_TILE;
    __nv_bfloat16* tKh = tQl + FS_TILE;
    __nv_bfloat16* tKl = tKh + FS_TILE;

    const int s0 = blockIdx.x * 64;
    const int bh = blockIdx.y;
    const int b  = bh >> 4;
    const int h  = bh & 15;
    const int tid = threadIdx.x, lane = tid & 31, wid = tid >> 5;
    const int wm = wid & 3, wn = wid >> 2;

    const uint32_t uQh = smem_to_u32(tQh);
    const uint32_t uQl = smem_to_u32(tQl);
    const uint32_t uKh = smem_to_u32(tKh);
    const uint32_t uKl = smem_to_u32(tKl);

    const int lr = tid >> 2;
    const int cb0 = (tid & 3) * 16;
    const char* gQh = (const char*)(g_Qh + ((size_t)(b * SEQ + s0 + lr)) * DMODEL + h * DK);
    const char* gQl = (const char*)(g_Ql + ((size_t)(b * SEQ + s0 + lr)) * DMODEL + h * DK);

#pragma unroll
    for (int j = 0; j < 2; j++) {
        int cb = cb0 + j * 64;
        cp_async16(uQh + lr * 144 + cb, gQh + cb);
        cp_async16(uQl + lr * 144 + cb, gQl + cb);
    }

    const int ntiles = s0 / 64 + 1;

    {
        const char* gKh = (const char*)(g_Kh + ((size_t)(b * SEQ + lr)) * DMODEL + h * DK);
        const char* gKl = (const char*)(g_Kl + ((size_t)(b * SEQ + lr)) * DMODEL + h * DK);
#pragma unroll
        for (int j = 0; j < 2; j++) {
            int cb = cb0 + j * 64;
            cp_async16(uKh + lr * 144 + cb, gKh + cb);
            cp_async16(uKl + lr * 144 + cb, gKl + cb);
        }
    }
    cp_commit();

    const int lrow = lane & 15;
    const int lcol = (lane >> 4) * 8;

    for (int t = 0; t < ntiles; t++) {
        const int t0 = t * 64;
        cp_wait0();
        __syncthreads();

        float c[4][4];
#pragma unroll
        for (int nf = 0; nf < 4; nf++)
#pragma unroll
            for (int j = 0; j < 4; j++) c[nf][j] = 0.f;

#pragma unroll
        for (int k0 = 0; k0 < 64; k0 += 16) {
            uint32_t aaddr_off = (uint32_t)((wm * 16 + lrow) * FS_TSTRIDE + k0 + lcol) * 2;
            uint32_t ah[4], al[4];
            LDSM_X4(ah[0], ah[1], ah[2], ah[3], uQh + aaddr_off);
            LDSM_X4(al[0], al[1], al[2], al[3], uQl + aaddr_off);
            uint32_t bhf[4][2], blf[4][2];
#pragma unroll
            for (int g = 0; g < 2; g++) {
                uint32_t baddr_off = (uint32_t)((wn * 32 + g * 16 + lrow) * FS_TSTRIDE + k0 + lcol) * 2;
                LDSM_X4(bhf[g * 2][0], bhf[g * 2 + 1][0],
                        bhf[g * 2][1], bhf[g * 2 + 1][1], uKh + baddr_off);
                LDSM_X4(blf[g * 2][0], blf[g * 2 + 1][0],
                        blf[g * 2][1], blf[g * 2 + 1][1], uKl + baddr_off);
            }
#pragma unroll
            for (int nf = 0; nf < 4; nf++) {
                MMA16816(c[nf], ah, bhf[nf]);
                MMA16816(c[nf], ah, blf[nf]);
                MMA16816(c[nf], al, bhf[nf]);
            }
        }

        {
            const int r0 = wm * 16 + (lane >> 2);
            const int sg0 = s0 + r0, sg1 = sg0 + 8;
#pragma unroll
            for (int nf = 0; nf < 4; nf++) {
                const int col = wn * 32 + nf * 8 + (lane & 3) * 2;
                const int tg = t0 + col;
                float2 rb0 = *reinterpret_cast<const float2*>(
                    rel_bias + ((size_t)h * SEQ + sg0) * SEQ + tg);
                float2 rb1 = *reinterpret_cast<const float2*>(
                    rel_bias + ((size_t)h * SEQ + sg1) * SEQ + tg);
                float v00 = c[nf][0] * 0.125f + rb0.x; if (tg     > sg0) v00 = -INFINITY;
                float v01 = c[nf][1] * 0.125f + rb0.y; if (tg + 1 > sg0) v01 = -INFINITY;
                float v10 = c[nf][2] * 0.125f + rb1.x; if (tg     > sg1) v10 = -INFINITY;
                float v11 = c[nf][3] * 0.125f + rb1.y; if (tg + 1 > sg1) v11 = -INFINITY;
                *reinterpret_cast<float2*>(&S[r0 * S_STRIDE + tg])       = make_float2(v00, v01);
                *reinterpret_cast<float2*>(&S[(r0 + 8) * S_STRIDE + tg]) = make_float2(v10, v11);
            }
        }
        __syncthreads();

        if (t + 1 < ntiles) {
            const int tn = (t + 1) * 64;
            const char* gKh = (const char*)(g_Kh + ((size_t)(b * SEQ + tn + lr)) * DMODEL + h * DK);
            const char* gKl = (const char*)(g_Kl + ((size_t)(b * SEQ + tn + lr)) * DMODEL + h * DK);
#pragma unroll
            for (int j = 0; j < 2; j++) {
                int cb = cb0 + j * 64;
                cp_async16(uKh + lr * 144 + cb, gKh + cb);
                cp_async16(uKl + lr * 144 + cb, gKl + cb);
            }
            cp_commit();
        }
    }

    __syncthreads();

    const int Lt = s0 + 64;
    for (int r = wid * 8; r < wid * 8 + 8; r++) {
        const int s = s0 + r;
        const int L = s + 1;
        float* row = S + r * S_STRIDE;

        float m = -INFINITY;
        for (int ci = lane; ci < L; ci += 32) m = fmaxf(m, row[ci]);
#pragma unroll
        for (int o = 16; o; o >>= 1) m = fmaxf(m, __shfl_xor_sync(0xffffffffu, m, o));

        float sum = 0.f;
        for (int ci = lane; ci < L; ci += 32) {
            float e = __expf(row[ci] - m);
            row[ci] = e;
            sum += e;
        }
#pragma unroll
        for (int o = 16; o; o >>= 1) sum += __shfl_xor_sync(0xffffffffu, sum, o);
        const float inv = 1.f / sum;

        __nv_bfloat16* oh = g_Ph + ((size_t)bh * SEQ + s) * SEQ;
        __nv_bfloat16* ol = g_Pl + ((size_t)bh * SEQ + s) * SEQ;
        for (int ci = lane; ci < Lt; ci += 32) {
            float p = (ci < L) ? row[ci] * inv : 0.f;
            __nv_bfloat16 ph = __float2bfloat16(p);
            oh[ci] = ph;
            ol[ci] = __float2bfloat16(p - __bfloat162float(ph));
        }
    }
}

// ===========================================================================
// ctx = P @ V via HMMA bf16x3 (ldmatrix.trans for V).
// ===========================================================================
__global__ void __launch_bounds__(256)
ctx_mma()
{
    __shared__ __align__(128) __nv_bfloat16 tPh[FS_TILE], tPl[FS_TILE], tVh[FS_TILE], tVl[FS_TILE];

    const int s0 = blockIdx.x * 64;
    const int bh = blockIdx.y;
    const int b  = bh >> 4;
    const int h  = bh & 15;
    const int tid = threadIdx.x, lane = tid & 31, wid = tid >> 5;
    const int wm = wid & 3, wn = wid >> 2;

    const uint32_t uPh = smem_to_u32(tPh);
    const uint32_t uPl = smem_to_u32(tPl);
    const uint32_t uVh = smem_to_u32(tVh);
    const uint32_t uVl = smem_to_u32(tVl);

    const int lr = tid >> 2;
    const int cb0 = (tid & 3) * 16;

    float c[4][4];
#pragma unroll
    for (int nf = 0; nf < 4; nf++)
#pragma unroll
        for (int j = 0; j < 4; j++) c[nf][j] = 0.f;

    const int ntiles = s0 / 64 + 1;

    auto load_tile = [&](int t0) {
        const char* gPh = (const char*)(g_Ph + ((size_t)bh * SEQ + s0 + lr) * SEQ + t0);
        const char* gPl = (const char*)(g_Pl + ((size_t)bh * SEQ + s0 + lr) * SEQ + t0);
        const char* gVh = (const char*)(g_Vh + ((size_t)(b * SEQ + t0 + lr)) * DMODEL + h * DK);
        const char* gVl = (const char*)(g_Vl + ((size_t)(b * SEQ + t0 + lr)) * DMODEL + h * DK);
#pragma unroll
        for (int j = 0; j < 2; j++) {
            int cb = cb0 + j * 64;
            cp_async16(uPh + lr * 144 + cb, gPh + cb);
            cp_async16(uPl + lr * 144 + cb, gPl + cb);
            cp_async16(uVh + lr * 144 + cb, gVh + cb);
            cp_async16(uVl + lr * 144 + cb, gVl + cb);
        }
    };

    load_tile(0);
    cp_commit();

    const int lrow = lane & 15;
    const int lcol = (lane >> 4) * 8;

    for (int t = 0; t < ntiles; t++) {
        cp_wait0();
        __syncthreads();

#pragma unroll
        for (int k0 = 0; k0 < 64; k0 += 16) {
            uint32_t aoff = (uint32_t)((wm * 16 + lrow) * FS_TSTRIDE + k0 + lcol) * 2;
            uint32_t ah[4], al[4];
            LDSM_X4(ah[0], ah[1], ah[2], ah[3], uPh + aoff);
            LDSM_X4(al[0], al[1], al[2], al[3], uPl + aoff);
            uint32_t bhf[4][2], blf[4][2];
#pragma unroll
            for (int g = 0; g < 2; g++) {
                uint32_t boff = (uint32_t)((k0 + lrow) * FS_TSTRIDE + wn * 32 + g * 16 + lcol) * 2;
                LDSM_X4_T(bhf[g * 2][0], bhf[g * 2][1],
                          bhf[g * 2 + 1][0], bhf[g * 2 + 1][1], uVh + boff);
                LDSM_X4_T(blf[g * 2][0], blf[g * 2][1],
                          blf[g * 2 + 1][0], blf[g * 2 + 1][1], uVl + boff);
            }
#pragma unroll
            for (int nf = 0; nf < 4; nf++) {
                MMA16816(c[nf], ah, bhf[nf]);
                MMA16816(c[nf], ah, blf[nf]);
                MMA16816(c[nf], al, bhf[nf]);
            }
        }
        __syncthreads();

        if (t + 1 < ntiles) {
            load_tile((t + 1) * 64);
            cp_commit();
        }
    }

    const int r0 = wm * 16 + (lane >> 2);
#pragma unroll
    for (int nf = 0; nf < 4; nf++) {
        const int col = wn * 32 + nf * 8 + (lane & 3) * 2;
#pragma unroll
        for (int half = 0; half < 2; half++) {
            const int s = s0 + r0 + half * 8;
            const float v0 = c[nf][half * 2], v1 = c[nf][half * 2 + 1];
            __nv_bfloat16 h0 = __float2bfloat16(v0);
            __nv_bfloat16 h1 = __float2bfloat16(v1);
            size_t o = ((size_t)(b * SEQ + s)) * DMODEL + h * DK + col;
            *reinterpret_cast<__nv_bfloat162*>(g_Ch + o) = __nv_bfloat162(h0, h1);
            *reinterpret_cast<__nv_bfloat162*>(g_Cl + o) = __nv_bfloat162(
                __float2bfloat16(v0 - __bfloat162float(h0)),
                __float2bfloat16(v1 - __bfloat162float(h1)));
        }
    }
}

// ===========================================================================
// attn head-mean
// ===========================================================================
__global__ void __launch_bounds__(256)
mean_kernel(float* __restrict__ out2)
{
    const size_t idx = (size_t)blockIdx.x * 256 + threadIdx.x;
    const int b = (int)(idx >> 18);
    const int r = (int)(idx & 262143);
    const int s = r >> 9;
    const int t = r & 511;
    if (t > s) { out2[idx] = 0.f; return; }
    float sum = 0.f;
#pragma unroll
    for (int h = 0; h < NHEAD; h++) {
        size_t o = ((size_t)(b * NHEAD + h) * SEQ + s) * SEQ + t;
        sum += __bfloat162float(g_Ph[o]) + __bfloat162float(g_Pl[o]);
    }
    out2[idx] = sum * (1.f / NHEAD);
}

// ===========================================================================
// Launch
// ===========================================================================
extern "C" void kernel_launch(void* const* d_in, const int* in_sizes, int n_in,
                              void* d_out, int out_size)
{
    const float* query = (const float*)d_in[0];
    const float* key   = (const float*)d_in[1];
    const float* value = (const float*)d_in[2];
    const float* wq_w  = (const float*)d_in[3];
    const float* wq_b  = (const float*)d_in[4];
    const float* wk_w  = (const float*)d_in[5];
    const float* wk_b  = (const float*)d_in[6];
    const float* wv_w  = (const float*)d_in[7];
    const float* wv_b  = (const float*)d_in[8];
    const float* wo_w  = (const float*)d_in[9];
    const float* wo_b  = (const float*)d_in[10];
    const float* rel_bias = (const float*)d_in[11];

    float* out  = (float*)d_out;
    const size_t out1_elems = (size_t)MTOT * DMODEL;
    const size_t out2_elems = (size_t)BATCH * SEQ * SEQ;
    float* out2 = out + out1_elems;

    __nv_bfloat16 *ahi, *alo, *whi, *wlo, *qh, *ql, *kh, *kl, *vh, *vl, *ch, *cl;
    cudaGetSymbolAddress((void**)&ahi, g_Ahi);
    cudaGetSymbolAddress((void**)&alo, g_Alo);
    cudaGetSymbolAddress((void**)&whi, g_Whi);
    cudaGetSymbolAddress((void**)&wlo, g_Wlo);
    cudaGetSymbolAddress((void**)&qh, g_Qh);
    cudaGetSymbolAddress((void**)&ql, g_Ql);
    cudaGetSymbolAddress((void**)&kh, g_Kh);
    cudaGetSymbolAddress((void**)&kl, g_Kl);
    cudaGetSymbolAddress((void**)&vh, g_Vh);
    cudaGetSymbolAddress((void**)&vl, g_Vl);
    cudaGetSymbolAddress((void**)&ch, g_Ch);
    cudaGetSymbolAddress((void**)&cl, g_Cl);

    cudaFuncSetAttribute(fused_scores_softmax,
                         cudaFuncAttributeMaxDynamicSharedMemorySize, FS_SMEM);
    cudaFuncSetAttribute(gemm_qkv,
                         cudaFuncAttributeMaxDynamicSharedMemorySize, GEMM_SMEM);
    cudaFuncSetAttribute(gemm_out,
                         cudaFuncAttributeMaxDynamicSharedMemorySize, GEMM_SMEM);

    const int nA4 = MTOT * DMODEL / 4;       // 2097152
    const int nW4 = DMODEL * DMODEL / 4;     // 262144
    const size_t wstride = (size_t)DMODEL * DMODEL;

    // splits: inputs (one fused launch) + 4 weights
    split3_bf16<<<dim3(nA4 / 256, 3), 256>>>(query, key, value, ahi, alo, nA4);
    split_bf16<<<nW4 / 256, 256>>>(wq_w, whi,               wlo,               nW4);
    split_bf16<<<nW4 / 256, 256>>>(wk_w, whi + wstride,     wlo + wstride,     nW4);
    split_bf16<<<nW4 / 256, 256>>>(wv_w, whi + 2 * wstride, wlo + 2 * wstride, nW4);
    split_bf16<<<nW4 / 256, 256>>>(wo_w, whi + 3 * wstride, wlo + 3 * wstride, nW4);

    // fused Q/K/V projections
    gemm_qkv<<<dim3(DMODEL / 128, MTOT / 128, 3), 256, GEMM_SMEM>>>(
        ahi, alo, whi, wlo, wq_b, wk_b, wv_b, qh, ql, kh, kl, vh, vl);

    // attention
    fused_scores_softmax<<<dim3(SEQ / 64, BH), 256, FS_SMEM>>>(rel_bias);

    if ((size_t)out_size >= out1_elems + out2_elems) {
        mean_kernel<<<(unsigned)(out2_elems / 256), 256>>>(out2);
    }

    ctx_mma<<<dim3(SEQ / 64, BH), 256>>>();

    // output projection
    gemm_out<<<dim3(DMODEL / 128, MTOT / 128), 256, GEMM_SMEM>>>(
        ch, cl, whi + 3 * wstride, wlo + 3 * wstride, wo_b, out);
}

// round 6
// speedup vs baseline: 1.9057x; 1.0124x over previous
#include <cuda_runtime.h>
#include <cuda_bf16.h>
#include <cstdint>
#include <math.h>

#define BATCH 16
#define SEQ   512
#define DMODEL 1024
#define NHEAD 16
#define DK    64
#define BH    (BATCH * NHEAD)
#define MTOT (BATCH * SEQ)

// ===========================================================================
// Portable PTX helpers
// ===========================================================================
__device__ __forceinline__ uint32_t smem_to_u32(const void* p) {
    uint32_t a;
    asm("{ .reg .u64 t; cvta.to.shared.u64 t, %1; cvt.u32.u64 %0, t; }" : "=r"(a) : "l"(p));
    return a;
}
__device__ __forceinline__ void cp_async16(uint32_t smem_addr, const void* gptr) {
    asm volatile("cp.async.cg.shared.global [%0], [%1], 16;" :: "r"(smem_addr), "l"(gptr) : "memory");
}
__device__ __forceinline__ void cp_commit() { asm volatile("cp.async.commit_group;" ::: "memory"); }
__device__ __forceinline__ void cp_wait2()  { asm volatile("cp.async.wait_group 2;" ::: "memory"); }
__device__ __forceinline__ void cp_wait0()  { asm volatile("cp.async.wait_group 0;" ::: "memory"); }

#define LDSM_X4(r0, r1, r2, r3, addr) \
    asm volatile("ldmatrix.sync.aligned.m8n8.x4.shared.b16 {%0,%1,%2,%3}, [%4];" \
        : "=r"(r0), "=r"(r1), "=r"(r2), "=r"(r3) : "r"(addr))

#define LDSM_X4_T(r0, r1, r2, r3, addr) \
    asm volatile("ldmatrix.sync.aligned.m8n8.x4.trans.shared.b16 {%0,%1,%2,%3}, [%4];" \
        : "=r"(r0), "=r"(r1), "=r"(r2), "=r"(r3) : "r"(addr))

#define MMA16816(c, a, b) \
    asm volatile("mma.sync.aligned.m16n8k16.row.col.f32.bf16.bf16.f32 " \
        "{%0,%1,%2,%3}, {%4,%5,%6,%7}, {%8,%9}, {%0,%1,%2,%3};" \
        : "+f"((c)[0]), "+f"((c)[1]), "+f"((c)[2]), "+f"((c)[3]) \
        : "r"((a)[0]), "r"((a)[1]), "r"((a)[2]), "r"((a)[3]), "r"((b)[0]), "r"((b)[1]))

// ===========================================================================
// Scratch
// ===========================================================================
__device__ __nv_bfloat16 g_Ahi[(size_t)3 * MTOT * DMODEL];
__device__ __nv_bfloat16 g_Alo[(size_t)3 * MTOT * DMODEL];
__device__ __nv_bfloat16 g_Whi[(size_t)4 * DMODEL * DMODEL];
__device__ __nv_bfloat16 g_Wlo[(size_t)4 * DMODEL * DMODEL];
__device__ __nv_bfloat16 g_Qh[(size_t)MTOT * DMODEL];
__device__ __nv_bfloat16 g_Ql[(size_t)MTOT * DMODEL];
__device__ __nv_bfloat16 g_Kh[(size_t)MTOT * DMODEL];
__device__ __nv_bfloat16 g_Kl[(size_t)MTOT * DMODEL];
__device__ __nv_bfloat16 g_Vh[(size_t)MTOT * DMODEL];
__device__ __nv_bfloat16 g_Vl[(size_t)MTOT * DMODEL];
__device__ __nv_bfloat16 g_Ch[(size_t)MTOT * DMODEL];
__device__ __nv_bfloat16 g_Cl[(size_t)MTOT * DMODEL];
__device__ __nv_bfloat16 g_Ph[(size_t)BH * SEQ * SEQ];   // hi only (for mean)

// ===========================================================================
// fp32 -> bf16 hi/lo splits
// ===========================================================================
__device__ __forceinline__ void split_store(const float4 v, __nv_bfloat16* hi,
                                            __nv_bfloat16* lo, size_t i4)
{
    __nv_bfloat16 h0 = __float2bfloat16(v.x);
    __nv_bfloat16 h1 = __float2bfloat16(v.y);
    __nv_bfloat16 h2 = __float2bfloat16(v.z);
    __nv_bfloat16 h3 = __float2bfloat16(v.w);
    __nv_bfloat162* hp = reinterpret_cast<__nv_bfloat162*>(hi);
    __nv_bfloat162* lp = reinterpret_cast<__nv_bfloat162*>(lo);
    hp[2 * i4]     = __nv_bfloat162(h0, h1);
    hp[2 * i4 + 1] = __nv_bfloat162(h2, h3);
    lp[2 * i4]     = __nv_bfloat162(__float2bfloat16(v.x - __bfloat162float(h0)),
                                    __float2bfloat16(v.y - __bfloat162float(h1)));
    lp[2 * i4 + 1] = __nv_bfloat162(__float2bfloat16(v.z - __bfloat162float(h2)),
                                    __float2bfloat16(v.w - __bfloat162float(h3)));
}

__global__ void __launch_bounds__(256)
split3_bf16(const float* __restrict__ q, const float* __restrict__ k,
            const float* __restrict__ v, __nv_bfloat16* __restrict__ hi,
            __nv_bfloat16* __restrict__ lo, int n4)
{
    int i = blockIdx.x * 256 + threadIdx.x;
    if (i >= n4) return;
    const int z = blockIdx.y;
    const float* src = (z == 0) ? q : ((z == 1) ? k : v);
    split_store(reinterpret_cast<const float4*>(src)[i], hi, lo, (size_t)z * n4 + i);
}

__global__ void __launch_bounds__(256)
split4_bf16(const float* __restrict__ w0, const float* __restrict__ w1,
            const float* __restrict__ w2, const float* __restrict__ w3,
            __nv_bfloat16* __restrict__ hi, __nv_bfloat16* __restrict__ lo, int n4)
{
    int i = blockIdx.x * 256 + threadIdx.x;
    if (i >= n4) return;
    const int z = blockIdx.y;
    const float* src = (z == 0) ? w0 : ((z == 1) ? w1 : ((z == 2) ? w2 : w3));
    split_store(reinterpret_cast<const float4*>(src)[i], hi, lo, (size_t)z * n4 + i);
}

// ===========================================================================
// HMMA GEMM core (bf16x3), 128x128 tile, BK=32, 4-stage cp.async pipeline.
// ===========================================================================
#define GK 1024
#define NK32 (GK / 32)
#define T_STRIDE 40
#define TILE_B (128 * T_STRIDE * 2)
#define STAGE_B (4 * TILE_B)
#define GEMM_SMEM (4 * STAGE_B)

__device__ __forceinline__ void
gemm_core(const __nv_bfloat16* __restrict__ Ahi, const __nv_bfloat16* __restrict__ Alo,
          const __nv_bfloat16* __restrict__ Bhi, const __nv_bfloat16* __restrict__ Blo,
          const float* __restrict__ bias, float* __restrict__ C,
          __nv_bfloat16* __restrict__ Chi, __nv_bfloat16* __restrict__ Clo,
          char* smem, int mBase, int nBase)
{
    const int tid  = threadIdx.x;
    const int lane = tid & 31;
    const int wid  = tid >> 5;
    const int wm   = wid & 3;
    const int wn   = wid >> 2;
    const uint32_t su32 = smem_to_u32(smem);

    float c[2][8][4];
#pragma unroll
    for (int mf = 0; mf < 2; mf++)
#pragma unroll
        for (int nf = 0; nf < 8; nf++)
#pragma unroll
            for (int j = 0; j < 4; j++) c[mf][nf][j] = 0.f;

    const int lr = tid >> 1;
    const int lk = (tid & 1) * 16;
    const __nv_bfloat16* gp0 = Ahi + (size_t)(mBase + lr) * GK + lk;
    const __nv_bfloat16* gp1 = Alo + (size_t)(mBase + lr) * GK + lk;
    const __nv_bfloat16* gp2 = Bhi + (size_t)(nBase + lr) * GK + lk;
    const __nv_bfloat16* gp3 = Blo + (size_t)(nBase + lr) * GK + lk;
    const uint32_t soff = (uint32_t)(lr * T_STRIDE + lk) * 2;

    auto load_chunk = [&](int st, int kc) {
        uint32_t base = su32 + (uint32_t)st * STAGE_B + soff;
        const int ko = kc * 32;
        cp_async16(base,               gp0 + ko);
        cp_async16(base + 16,          gp0 + ko + 8);
        cp_async16(base + TILE_B,      gp1 + ko);
        cp_async16(base + TILE_B + 16, gp1 + ko + 8);
        cp_async16(base + 2 * TILE_B,      gp2 + ko);
        cp_async16(base + 2 * TILE_B + 16, gp2 + ko + 8);
        cp_async16(base + 3 * TILE_B,      gp3 + ko);
        cp_async16(base + 3 * TILE_B + 16, gp3 + ko + 8);
    };

    load_chunk(0, 0); cp_commit();
    load_chunk(1, 1); cp_commit();
    load_chunk(2, 2); cp_commit();

    const int lrow = lane & 15;
    const int lcol = (lane >> 4) * 8;

    for (int i = 0; i < NK32; i++) {
        cp_wait2();
        __syncthreads();
        if (i + 3 < NK32) load_chunk((i + 3) & 3, i + 3);
        cp_commit();

        const uint32_t sb = su32 + (uint32_t)(i & 3) * STAGE_B;
#pragma unroll
        for (int kh = 0; kh < 32; kh += 16) {
            uint32_t bh[8][2], bl[8][2];
#pragma unroll
            for (int g = 0; g < 4; g++) {
                uint32_t addr = sb + 2 * TILE_B +
                    (uint32_t)((wn * 64 + g * 16 + lrow) * T_STRIDE + kh + lcol) * 2;
                LDSM_X4(bh[g * 2][0], bh[g * 2 + 1][0],
                        bh[g * 2][1], bh[g * 2 + 1][1], addr);
                LDSM_X4(bl[g * 2][0], bl[g * 2 + 1][0],
                        bl[g * 2][1], bl[g * 2 + 1][1], addr + TILE_B);
            }
#pragma unroll
            for (int mf = 0; mf < 2; mf++) {
                uint32_t aaddr = sb +
                    (uint32_t)((wm * 32 + mf * 16 + lrow) * T_STRIDE + kh + lcol) * 2;
                uint32_t ah[4], al[4];
                LDSM_X4(ah[0], ah[1], ah[2], ah[3], aaddr);
                LDSM_X4(al[0], al[1], al[2], al[3], aaddr + TILE_B);
#pragma unroll
                for (int nf = 0; nf < 8; nf++) {
                    MMA16816(c[mf][nf], ah, bh[nf]);
                    MMA16816(c[mf][nf], ah, bl[nf]);
                    MMA16816(c[mf][nf], al, bh[nf]);
                }
            }
        }
    }

#pragma unroll
    for (int mf = 0; mf < 2; mf++) {
        const int row0 = mBase + wm * 32 + mf * 16 + (lane >> 2);
#pragma unroll
        for (int nf = 0; nf < 8; nf++) {
            const int col = nBase + wn * 64 + nf * 8 + (lane & 3) * 2;
            const float b0 = bias[col], b1 = bias[col + 1];
            float v00 = c[mf][nf][0] + b0, v01 = c[mf][nf][1] + b1;
            float v10 = c[mf][nf][2] + b0, v11 = c[mf][nf][3] + b1;
            if (Chi) {
                __nv_bfloat16 h00 = __float2bfloat16(v00), h01 = __float2bfloat16(v01);
                __nv_bfloat16 h10 = __float2bfloat16(v10), h11 = __float2bfloat16(v11);
                size_t o0 = (size_t)row0 * DMODEL + col, o1 = (size_t)(row0 + 8) * DMODEL + col;
                *reinterpret_cast<__nv_bfloat162*>(Chi + o0) = __nv_bfloat162(h00, h01);
                *reinterpret_cast<__nv_bfloat162*>(Chi + o1) = __nv_bfloat162(h10, h11);
                *reinterpret_cast<__nv_bfloat162*>(Clo + o0) = __nv_bfloat162(
                    __float2bfloat16(v00 - __bfloat162float(h00)),
                    __float2bfloat16(v01 - __bfloat162float(h01)));
                *reinterpret_cast<__nv_bfloat162*>(Clo + o1) = __nv_bfloat162(
                    __float2bfloat16(v10 - __bfloat162float(h10)),
                    __float2bfloat16(v11 - __bfloat162float(h11)));
            } else {
                *reinterpret_cast<float2*>(C + (size_t)row0 * DMODEL + col)       = make_float2(v00, v01);
                *reinterpret_cast<float2*>(C + (size_t)(row0 + 8) * DMODEL + col) = make_float2(v10, v11);
            }
        }
    }
}

__global__ void __launch_bounds__(256)
gemm_qkv(const __nv_bfloat16* __restrict__ Ahi, const __nv_bfloat16* __restrict__ Alo,
         const __nv_bfloat16* __restrict__ Whi, const __nv_bfloat16* __restrict__ Wlo,
         const float* __restrict__ b0, const float* __restrict__ b1, const float* __restrict__ b2,
         __nv_bfloat16* __restrict__ o0h, __nv_bfloat16* __restrict__ o0l,
         __nv_bfloat16* __restrict__ o1h, __nv_bfloat16* __restrict__ o1l,
         __nv_bfloat16* __restrict__ o2h, __nv_bfloat16* __restrict__ o2l)
{
    extern __shared__ __align__(128) char smem[];
    const int z = blockIdx.z;
    const size_t aoff = (size_t)z * MTOT * GK;
    const size_t woff = (size_t)z * DMODEL * GK;
    const float* bias = (z == 0) ? b0 : ((z == 1) ? b1 : b2);
    __nv_bfloat16* oh = (z == 0) ? o0h : ((z == 1) ? o1h : o2h);
    __nv_bfloat16* ol = (z == 0) ? o0l : ((z == 1) ? o1l : o2l);
    gemm_core(Ahi + aoff, Alo + aoff, Whi + woff, Wlo + woff,
              bias, nullptr, oh, ol, smem, blockIdx.y * 128, blockIdx.x * 128);
}

__global__ void __launch_bounds__(256)
gemm_out(const __nv_bfloat16* __restrict__ Ahi, const __nv_bfloat16* __restrict__ Alo,
         const __nv_bfloat16* __restrict__ Whi, const __nv_bfloat16* __restrict__ Wlo,
         const float* __restrict__ bias, float* __restrict__ C)
{
    extern __shared__ __align__(128) char smem[];
    gemm_core(Ahi, Alo, Whi, Wlo, bias, C, nullptr, nullptr,
              smem, blockIdx.y * 128, blockIdx.x * 128);
}

// ===========================================================================
// Fully fused attention: scores (HMMA) + softmax + ctx (HMMA).
// One CTA per (bh, 64 s-rows). P-lo never leaves smem; P-hi stored for mean.
// ===========================================================================
#define S_STRIDE 516
#define FS_SBYTES (64 * S_STRIDE * 4)          // 132096
#define FS_TSTRIDE 72
#define FS_TILE (64 * FS_TSTRIDE)
#define FS_SMEM (FS_SBYTES + 4 * FS_TILE * 2)  // 168960

__global__ void __launch_bounds__(256)
fused_attention(const float* __restrict__ rel_bias)
{
    extern __shared__ __align__(128) char fsmem[];
    float* S = reinterpret_cast<float*>(fsmem);
    __nv_bfloat16* tA = reinterpret_cast<__nv_bfloat16*>(fsmem + FS_SBYTES);  // Qh / Ph
    __nv_bfloat16* tB = tA + FS_TILE;                                         // Ql / Pl
    __nv_bfloat16* tC = tB + FS_TILE;                                         // Kh / Vh
    __nv_bfloat16* tD = tC + FS_TILE;                                         // Kl / Vl

    const int s0 = (gridDim.x - 1 - blockIdx.x) * 64;   // heavy tiles first
    const int bh = blockIdx.y;
    const int b  = bh >> 4;
    const int h  = bh & 15;
    const int tid = threadIdx.x, lane = tid & 31, wid = tid >> 5;
    const int wm = wid & 3, wn = wid >> 2;

    const uint32_t uA = smem_to_u32(tA);
    const uint32_t uB = smem_to_u32(tB);
    const uint32_t uC = smem_to_u32(tC);
    const uint32_t uD = smem_to_u32(tD);

    const int lr = tid >> 2;
    const int cb0 = (tid & 3) * 16;
    const int ntiles = s0 / 64 + 1;
    const int lrow = lane & 15;
    const int lcol = (lane >> 4) * 8;

    // ---------------- Phase 1: scores -> S ----------------
    {
        const char* gQh = (const char*)(g_Qh + ((size_t)(b * SEQ + s0 + lr)) * DMODEL + h * DK);
        const char* gQl = (const char*)(g_Ql + ((size_t)(b * SEQ + s0 + lr)) * DMODEL + h * DK);
#pragma unroll
        for (int j = 0; j < 2; j++) {
            int cb = cb0 + j * 64;
            cp_async16(uA + lr * 144 + cb, gQh + cb);
            cp_async16(uB + lr * 144 + cb, gQl + cb);
        }
        const char* gKh = (const char*)(g_Kh + ((size_t)(b * SEQ + lr)) * DMODEL + h * DK);
        const char* gKl = (const char*)(g_Kl + ((size_t)(b * SEQ + lr)) * DMODEL + h * DK);
#pragma unroll
        for (int j = 0; j < 2; j++) {
            int cb = cb0 + j * 64;
            cp_async16(uC + lr * 144 + cb, gKh + cb);
            cp_async16(uD + lr * 144 + cb, gKl + cb);
        }
        cp_commit();
    }

    for (int t = 0; t < ntiles; t++) {
        const int t0 = t * 64;
        cp_wait0();
        __syncthreads();

        float c[4][4];
#pragma unroll
        for (int nf = 0; nf < 4; nf++)
#pragma unroll
            for (int j = 0; j < 4; j++) c[nf][j] = 0.f;

#pragma unroll
        for (int k0 = 0; k0 < 64; k0 += 16) {
            uint32_t aoff = (uint32_t)((wm * 16 + lrow) * FS_TSTRIDE + k0 + lcol) * 2;
            uint32_t ah[4], al[4];
            LDSM_X4(ah[0], ah[1], ah[2], ah[3], uA + aoff);
            LDSM_X4(al[0], al[1], al[2], al[3], uB + aoff);
            uint32_t bhf[4][2], blf[4][2];
#pragma unroll
            for (int g = 0; g < 2; g++) {
                uint32_t boff = (uint32_t)((wn * 32 + g * 16 + lrow) * FS_TSTRIDE + k0 + lcol) * 2;
                LDSM_X4(bhf[g * 2][0], bhf[g * 2 + 1][0],
                        bhf[g * 2][1], bhf[g * 2 + 1][1], uC + boff);
                LDSM_X4(blf[g * 2][0], blf[g * 2 + 1][0],
                        blf[g * 2][1], blf[g * 2 + 1][1], uD + boff);
            }
#pragma unroll
            for (int nf = 0; nf < 4; nf++) {
                MMA16816(c[nf], ah, bhf[nf]);
                MMA16816(c[nf], ah, blf[nf]);
                MMA16816(c[nf], al, bhf[nf]);
            }
        }

        {
            const int r0 = wm * 16 + (lane >> 2);
            const int sg0 = s0 + r0, sg1 = sg0 + 8;
#pragma unroll
            for (int nf = 0; nf < 4; nf++) {
                const int col = wn * 32 + nf * 8 + (lane & 3) * 2;
                const int tg = t0 + col;
                float2 rb0 = *reinterpret_cast<const float2*>(
                    rel_bias + ((size_t)h * SEQ + sg0) * SEQ + tg);
                float2 rb1 = *reinterpret_cast<const float2*>(
                    rel_bias + ((size_t)h * SEQ + sg1) * SEQ + tg);
                float v00 = c[nf][0] * 0.125f + rb0.x; if (tg     > sg0) v00 = -INFINITY;
                float v01 = c[nf][1] * 0.125f + rb0.y; if (tg + 1 > sg0) v01 = -INFINITY;
                float v10 = c[nf][2] * 0.125f + rb1.x; if (tg     > sg1) v10 = -INFINITY;
                float v11 = c[nf][3] * 0.125f + rb1.y; if (tg + 1 > sg1) v11 = -INFINITY;
                *reinterpret_cast<float2*>(&S[r0 * S_STRIDE + tg])       = make_float2(v00, v01);
                *reinterpret_cast<float2*>(&S[(r0 + 8) * S_STRIDE + tg]) = make_float2(v10, v11);
            }
        }
        __syncthreads();

        if (t + 1 < ntiles) {
            const int tn = (t + 1) * 64;
            const char* gKh = (const char*)(g_Kh + ((size_t)(b * SEQ + tn + lr)) * DMODEL + h * DK);
            const char* gKl = (const char*)(g_Kl + ((size_t)(b * SEQ + tn + lr)) * DMODEL + h * DK);
#pragma unroll
            for (int j = 0; j < 2; j++) {
                int cb = cb0 + j * 64;
                cp_async16(uC + lr * 144 + cb, gKh + cb);
                cp_async16(uD + lr * 144 + cb, gKl + cb);
            }
            cp_commit();
        }
    }
    __syncthreads();

    // ---------------- Phase 2: softmax (P stays fp32 in S; hi to DRAM) ------
    const int Lt = s0 + 64;
    for (int r = wid * 8; r < wid * 8 + 8; r++) {
        const int s = s0 + r;
        const int L = s + 1;
        float* row = S + r * S_STRIDE;

        float m = -INFINITY;
        for (int ci = lane; ci < L; ci += 32) m = fmaxf(m, row[ci]);
#pragma unroll
        for (int o = 16; o; o >>= 1) m = fmaxf(m, __shfl_xor_sync(0xffffffffu, m, o));

        float sum = 0.f;
        for (int ci = lane; ci < L; ci += 32) {
            float e = __expf(row[ci] - m);
            row[ci] = e;
            sum += e;
        }
#pragma unroll
        for (int o = 16; o; o >>= 1) sum += __shfl_xor_sync(0xffffffffu, sum, o);
        const float inv = 1.f / sum;

        __nv_bfloat16* oh = g_Ph + ((size_t)bh * SEQ + s) * SEQ;
        for (int ci = lane; ci < Lt; ci += 32) {
            float p = (ci < L) ? row[ci] * inv : 0.f;
            row[ci] = p;
            oh[ci] = __float2bfloat16(p);
        }
    }
    __syncthreads();

    // ---------------- Phase 3: ctx = P @ V ----------------
    float c[4][4];
#pragma unroll
    for (int nf = 0; nf < 4; nf++)
#pragma unroll
        for (int j = 0; j < 4; j++) c[nf][j] = 0.f;

    for (int t = 0; t < ntiles; t++) {
        const int t0 = t * 64;
        // issue V tile load (overlaps with P conversion)
        {
            const char* gVh = (const char*)(g_Vh + ((size_t)(b * SEQ + t0 + lr)) * DMODEL + h * DK);
            const char* gVl = (const char*)(g_Vl + ((size_t)(b * SEQ + t0 + lr)) * DMODEL + h * DK);
#pragma unroll
            for (int j = 0; j < 2; j++) {
                int cb = cb0 + j * 64;
                cp_async16(uC + lr * 144 + cb, gVh + cb);
                cp_async16(uD + lr * 144 + cb, gVl + cb);
            }
            cp_commit();
        }
        // convert S[:, t0:t0+64] -> tA (hi), tB (lo)
        {
            const float* srow = S + lr * S_STRIDE + t0 + cb0;
            __nv_bfloat16* ph = tA + lr * FS_TSTRIDE + cb0;
            __nv_bfloat16* pl = tB + lr * FS_TSTRIDE + cb0;
#pragma unroll
            for (int q = 0; q < 4; q++) {
                float4 v = *reinterpret_cast<const float4*>(srow + q * 4);
                __nv_bfloat16 h0 = __float2bfloat16(v.x);
                __nv_bfloat16 h1 = __float2bfloat16(v.y);
                __nv_bfloat16 h2 = __float2bfloat16(v.z);
                __nv_bfloat16 h3 = __float2bfloat16(v.w);
                *reinterpret_cast<__nv_bfloat162*>(ph + q * 4)     = __nv_bfloat162(h0, h1);
                *reinterpret_cast<__nv_bfloat162*>(ph + q * 4 + 2) = __nv_bfloat162(h2, h3);
                *reinterpret_cast<__nv_bfloat162*>(pl + q * 4)     = __nv_bfloat162(
                    __float2bfloat16(v.x - __bfloat162float(h0)),
                    __float2bfloat16(v.y - __bfloat162float(h1)));
                *reinterpret_cast<__nv_bfloat162*>(pl + q * 4 + 2) = __nv_bfloat162(
                    __float2bfloat16(v.z - __bfloat162float(h2)),
                    __float2bfloat16(v.w - __bfloat162float(h3)));
            }
        }
        cp_wait0();
        __syncthreads();

#pragma unroll
        for (int k0 = 0; k0 < 64; k0 += 16) {
            uint32_t aoff = (uint32_t)((wm * 16 + lrow) * FS_TSTRIDE + k0 + lcol) * 2;
            uint32_t ah[4], al[4];
            LDSM_X4(ah[0], ah[1], ah[2], ah[3], uA + aoff);
            LDSM_X4(al[0], al[1], al[2], al[3], uB + aoff);
            uint32_t bhf[4][2], blf[4][2];
#pragma unroll
            for (int g = 0; g < 2; g++) {
                uint32_t boff = (uint32_t)((k0 + lrow) * FS_TSTRIDE + wn * 32 + g * 16 + lcol) * 2;
                LDSM_X4_T(bhf[g * 2][0], bhf[g * 2][1],
                          bhf[g * 2 + 1][0], bhf[g * 2 + 1][1], uC + boff);
                LDSM_X4_T(blf[g * 2][0], blf[g * 2][1],
                          blf[g * 2 + 1][0], blf[g * 2 + 1][1], uD + boff);
            }
#pragma unroll
            for (int nf = 0; nf < 4; nf++) {
                MMA16816(c[nf], ah, bhf[nf]);
                MMA16816(c[nf], ah, blf[nf]);
                MMA16816(c[nf], al, bhf[nf]);
            }
        }
        __syncthreads();
    }

    // ctx epilogue -> g_Ch / g_Cl
    const int r0 = wm * 16 + (lane >> 2);
#pragma unroll
    for (int nf = 0; nf < 4; nf++) {
        const int col = wn * 32 + nf * 8 + (lane & 3) * 2;
#pragma unroll
        for (int half = 0; half < 2; half++) {
            const int s = s0 + r0 + half * 8;
            const float v0 = c[nf][half * 2], v1 = c[nf][half * 2 + 1];
            __nv_bfloat16 h0 = __float2bfloat16(v0);
            __nv_bfloat16 h1 = __float2bfloat16(v1);
            size_t o = ((size_t)(b * SEQ + s)) * DMODEL + h * DK + col;
            *reinterpret_cast<__nv_bfloat162*>(g_Ch + o) = __nv_bfloat162(h0, h1);
            *reinterpret_cast<__nv_bfloat162*>(g_Cl + o) = __nv_bfloat162(
                __float2bfloat16(v0 - __bfloat162float(h0)),
                __float2bfloat16(v1 - __bfloat162float(h1)));
        }
    }
}

// ===========================================================================
// attn head-mean (bf16-hi P; causal-bounded)
// ===========================================================================
__global__ void __launch_bounds__(256)
mean_kernel(float* __restrict__ out2)
{
    const size_t idx = (size_t)blockIdx.x * 256 + threadIdx.x;
    const int b = (int)(idx >> 18);
    const int r = (int)(idx & 262143);
    const int s = r >> 9;
    const int t = r & 511;
    if (t > s) { out2[idx] = 0.f; return; }
    float sum = 0.f;
#pragma unroll
    for (int h = 0; h < NHEAD; h++) {
        sum += __bfloat162float(g_Ph[((size_t)(b * NHEAD + h) * SEQ + s) * SEQ + t]);
    }
    out2[idx] = sum * (1.f / NHEAD);
}

// ===========================================================================
// Launch
// ===========================================================================
extern "C" void kernel_launch(void* const* d_in, const int* in_sizes, int n_in,
                              void* d_out, int out_size)
{
    const float* query = (const float*)d_in[0];
    const float* key   = (const float*)d_in[1];
    const float* value = (const float*)d_in[2];
    const float* wq_w  = (const float*)d_in[3];
    const float* wq_b  = (const float*)d_in[4];
    const float* wk_w  = (const float*)d_in[5];
    const float* wk_b  = (const float*)d_in[6];
    const float* wv_w  = (const float*)d_in[7];
    const float* wv_b  = (const float*)d_in[8];
    const float* wo_w  = (const float*)d_in[9];
    const float* wo_b  = (const float*)d_in[10];
    const float* rel_bias = (const float*)d_in[11];

    float* out  = (float*)d_out;
    const size_t out1_elems = (size_t)MTOT * DMODEL;
    const size_t out2_elems = (size_t)BATCH * SEQ * SEQ;
    float* out2 = out + out1_elems;

    __nv_bfloat16 *ahi, *alo, *whi, *wlo, *qh, *ql, *kh, *kl, *vh, *vl, *ch, *cl;
    cudaGetSymbolAddress((void**)&ahi, g_Ahi);
    cudaGetSymbolAddress((void**)&alo, g_Alo);
    cudaGetSymbolAddress((void**)&whi, g_Whi);
    cudaGetSymbolAddress((void**)&wlo, g_Wlo);
    cudaGetSymbolAddress((void**)&qh, g_Qh);
    cudaGetSymbolAddress((void**)&ql, g_Ql);
    cudaGetSymbolAddress((void**)&kh, g_Kh);
    cudaGetSymbolAddress((void**)&kl, g_Kl);
    cudaGetSymbolAddress((void**)&vh, g_Vh);
    cudaGetSymbolAddress((void**)&vl, g_Vl);
    cudaGetSymbolAddress((void**)&ch, g_Ch);
    cudaGetSymbolAddress((void**)&cl, g_Cl);

    cudaFuncSetAttribute(fused_attention,
                         cudaFuncAttributeMaxDynamicSharedMemorySize, FS_SMEM);
    cudaFuncSetAttribute(gemm_qkv,
                         cudaFuncAttributeMaxDynamicSharedMemorySize, GEMM_SMEM);
    cudaFuncSetAttribute(gemm_out,
                         cudaFuncAttributeMaxDynamicSharedMemorySize, GEMM_SMEM);

    const int nA4 = MTOT * DMODEL / 4;
    const int nW4 = DMODEL * DMODEL / 4;
    const size_t wstride = (size_t)DMODEL * DMODEL;

    split3_bf16<<<dim3(nA4 / 256, 3), 256>>>(query, key, value, ahi, alo, nA4);
    split4_bf16<<<dim3(nW4 / 256, 4), 256>>>(wq_w, wk_w, wv_w, wo_w, whi, wlo, nW4);

    gemm_qkv<<<dim3(DMODEL / 128, MTOT / 128, 3), 256, GEMM_SMEM>>>(
        ahi, alo, whi, wlo, wq_b, wk_b, wv_b, qh, ql, kh, kl, vh, vl);

    fused_attention<<<dim3(SEQ / 64, BH), 256, FS_SMEM>>>(rel_bias);

    if ((size_t)out_size >= out1_elems + out2_elems) {
        mean_kernel<<<(unsigned)(out2_elems / 256), 256>>>(out2);
    }

    gemm_out<<<dim3(DMODEL / 128, MTOT / 128), 256, GEMM_SMEM>>>(
        ch, cl, whi + 3 * wstride, wlo + 3 * wstride, wo_b, out);
}

// round 8
// speedup vs baseline: 2.0456x; 1.0734x over previous
#include <cuda_runtime.h>
#include <cuda_bf16.h>
#include <cuda_fp16.h>
#include <cstdint>
#include <math.h>

#define BATCH 16
#define SEQ   512
#define DMODEL 1024
#define NHEAD 16
#define DK    64
#define BH    (BATCH * NHEAD)
#define MTOT (BATCH * SEQ)

// ===========================================================================
// Portable PTX helpers
// ===========================================================================
__device__ __forceinline__ uint32_t smem_to_u32(const void* p) {
    uint32_t a;
    asm("{ .reg .u64 t; cvta.to.shared.u64 t, %1; cvt.u32.u64 %0, t; }" : "=r"(a) : "l"(p));
    return a;
}
__device__ __forceinline__ void cp_async16(uint32_t smem_addr, const void* gptr) {
    asm volatile("cp.async.cg.shared.global [%0], [%1], 16;" :: "r"(smem_addr), "l"(gptr) : "memory");
}
__device__ __forceinline__ void cp_commit() { asm volatile("cp.async.commit_group;" ::: "memory"); }
__device__ __forceinline__ void cp_wait2()  { asm volatile("cp.async.wait_group 2;" ::: "memory"); }
__device__ __forceinline__ void cp_wait1()  { asm volatile("cp.async.wait_group 1;" ::: "memory"); }
__device__ __forceinline__ void cp_wait0()  { asm volatile("cp.async.wait_group 0;" ::: "memory"); }

#define LDSM_X4(r0, r1, r2, r3, addr) \
    asm volatile("ldmatrix.sync.aligned.m8n8.x4.shared.b16 {%0,%1,%2,%3}, [%4];" \
        : "=r"(r0), "=r"(r1), "=r"(r2), "=r"(r3) : "r"(addr))

#define LDSM_X4_T(r0, r1, r2, r3, addr) \
    asm volatile("ldmatrix.sync.aligned.m8n8.x4.trans.shared.b16 {%0,%1,%2,%3}, [%4];" \
        : "=r"(r0), "=r"(r1), "=r"(r2), "=r"(r3) : "r"(addr))

#define MMA16816(c, a, b) \
    asm volatile("mma.sync.aligned.m16n8k16.row.col.f32.bf16.bf16.f32 " \
        "{%0,%1,%2,%3}, {%4,%5,%6,%7}, {%8,%9}, {%0,%1,%2,%3};" \
        : "+f"((c)[0]), "+f"((c)[1]), "+f"((c)[2]), "+f"((c)[3]) \
        : "r"((a)[0]), "r"((a)[1]), "r"((a)[2]), "r"((a)[3]), "r"((b)[0]), "r"((b)[1]))

// ===========================================================================
// Scratch
// ===========================================================================
__device__ __nv_bfloat16 g_Ahi[(size_t)3 * MTOT * DMODEL];
__device__ __nv_bfloat16 g_Alo[(size_t)3 * MTOT * DMODEL];
__device__ __nv_bfloat16 g_Whi[(size_t)4 * DMODEL * DMODEL];
__device__ __nv_bfloat16 g_Wlo[(size_t)4 * DMODEL * DMODEL];
__device__ __nv_bfloat16 g_Qh[(size_t)MTOT * DMODEL];
__device__ __nv_bfloat16 g_Ql[(size_t)MTOT * DMODEL];
__device__ __nv_bfloat16 g_Kh[(size_t)MTOT * DMODEL];
__device__ __nv_bfloat16 g_Kl[(size_t)MTOT * DMODEL];
__device__ __nv_bfloat16 g_Vh[(size_t)MTOT * DMODEL];
__device__ __nv_bfloat16 g_Vl[(size_t)MTOT * DMODEL];
__device__ __nv_bfloat16 g_Ch[(size_t)MTOT * DMODEL];
__device__ __nv_bfloat16 g_Cl[(size_t)MTOT * DMODEL];
__device__ __half g_Pm[(size_t)BH * SEQ * SEQ];   // fp16 P (for mean)

// ===========================================================================
// fp32 -> bf16 hi/lo splits
// ===========================================================================
__device__ __forceinline__ void split_store(const float4 v, __nv_bfloat16* hi,
                                            __nv_bfloat16* lo, size_t i4)
{
    __nv_bfloat16 h0 = __float2bfloat16(v.x);
    __nv_bfloat16 h1 = __float2bfloat16(v.y);
    __nv_bfloat16 h2 = __float2bfloat16(v.z);
    __nv_bfloat16 h3 = __float2bfloat16(v.w);
    __nv_bfloat162* hp = reinterpret_cast<__nv_bfloat162*>(hi);
    __nv_bfloat162* lp = reinterpret_cast<__nv_bfloat162*>(lo);
    hp[2 * i4]     = __nv_bfloat162(h0, h1);
    hp[2 * i4 + 1] = __nv_bfloat162(h2, h3);
    lp[2 * i4]     = __nv_bfloat162(__float2bfloat16(v.x - __bfloat162float(h0)),
                                    __float2bfloat16(v.y - __bfloat162float(h1)));
    lp[2 * i4 + 1] = __nv_bfloat162(__float2bfloat16(v.z - __bfloat162float(h2)),
                                    __float2bfloat16(v.w - __bfloat162float(h3)));
}

__global__ void __launch_bounds__(256)
split3_bf16(const float* __restrict__ q, const float* __restrict__ k,
            const float* __restrict__ v, __nv_bfloat16* __restrict__ hi,
            __nv_bfloat16* __restrict__ lo, int n4)
{
    int i = blockIdx.x * 256 + threadIdx.x;
    if (i >= n4) return;
    const int z = blockIdx.y;
    const float* src = (z == 0) ? q : ((z == 1) ? k : v);
    split_store(reinterpret_cast<const float4*>(src)[i], hi, lo, (size_t)z * n4 + i);
}

__global__ void __launch_bounds__(256)
split4_bf16(const float* __restrict__ w0, const float* __restrict__ w1,
            const float* __restrict__ w2, const float* __restrict__ w3,
            __nv_bfloat16* __restrict__ hi, __nv_bfloat16* __restrict__ lo, int n4)
{
    int i = blockIdx.x * 256 + threadIdx.x;
    if (i >= n4) return;
    const int z = blockIdx.y;
    const float* src = (z == 0) ? w0 : ((z == 1) ? w1 : ((z == 2) ? w2 : w3));
    split_store(reinterpret_cast<const float4*>(src)[i], hi, lo, (size_t)z * n4 + i);
}

// ===========================================================================
// HMMA GEMM core (bf16x3), 128x128 tile, BK=32, 4-stage cp.async pipeline.
// ===========================================================================
#define GK 1024
#define NK32 (GK / 32)
#define T_STRIDE 40
#define TILE_B (128 * T_STRIDE * 2)
#define STAGE_B (4 * TILE_B)
#define GEMM_SMEM (4 * STAGE_B)

__device__ __forceinline__ void
gemm_core(const __nv_bfloat16* __restrict__ Ahi, const __nv_bfloat16* __restrict__ Alo,
          const __nv_bfloat16* __restrict__ Bhi, const __nv_bfloat16* __restrict__ Blo,
          const float* __restrict__ bias, float* __restrict__ C,
          __nv_bfloat16* __restrict__ Chi, __nv_bfloat16* __restrict__ Clo,
          char* smem, int mBase, int nBase)
{
    const int tid  = threadIdx.x;
    const int lane = tid & 31;
    const int wid  = tid >> 5;
    const int wm   = wid & 3;
    const int wn   = wid >> 2;
    const uint32_t su32 = smem_to_u32(smem);

    float c[2][8][4];
#pragma unroll
    for (int mf = 0; mf < 2; mf++)
#pragma unroll
        for (int nf = 0; nf < 8; nf++)
#pragma unroll
            for (int j = 0; j < 4; j++) c[mf][nf][j] = 0.f;

    const int lr = tid >> 1;
    const int lk = (tid & 1) * 16;
    const __nv_bfloat16* gp0 = Ahi + (size_t)(mBase + lr) * GK + lk;
    const __nv_bfloat16* gp1 = Alo + (size_t)(mBase + lr) * GK + lk;
    const __nv_bfloat16* gp2 = Bhi + (size_t)(nBase + lr) * GK + lk;
    const __nv_bfloat16* gp3 = Blo + (size_t)(nBase + lr) * GK + lk;
    const uint32_t soff = (uint32_t)(lr * T_STRIDE + lk) * 2;

    auto load_chunk = [&](int st, int kc) {
        uint32_t base = su32 + (uint32_t)st * STAGE_B + soff;
        const int ko = kc * 32;
        cp_async16(base,               gp0 + ko);
        cp_async16(base + 16,          gp0 + ko + 8);
        cp_async16(base + TILE_B,      gp1 + ko);
        cp_async16(base + TILE_B + 16, gp1 + ko + 8);
        cp_async16(base + 2 * TILE_B,      gp2 + ko);
        cp_async16(base + 2 * TILE_B + 16, gp2 + ko + 8);
        cp_async16(base + 3 * TILE_B,      gp3 + ko);
        cp_async16(base + 3 * TILE_B + 16, gp3 + ko + 8);
    };

    load_chunk(0, 0); cp_commit();
    load_chunk(1, 1); cp_commit();
    load_chunk(2, 2); cp_commit();

    const int lrow = lane & 15;
    const int lcol = (lane >> 4) * 8;

    for (int i = 0; i < NK32; i++) {
        cp_wait2();
        __syncthreads();
        if (i + 3 < NK32) load_chunk((i + 3) & 3, i + 3);
        cp_commit();

        const uint32_t sb = su32 + (uint32_t)(i & 3) * STAGE_B;
#pragma unroll
        for (int kh = 0; kh < 32; kh += 16) {
            uint32_t bh[8][2], bl[8][2];
#pragma unroll
            for (int g = 0; g < 4; g++) {
                uint32_t addr = sb + 2 * TILE_B +
                    (uint32_t)((wn * 64 + g * 16 + lrow) * T_STRIDE + kh + lcol) * 2;
                LDSM_X4(bh[g * 2][0], bh[g * 2 + 1][0],
                        bh[g * 2][1], bh[g * 2 + 1][1], addr);
                LDSM_X4(bl[g * 2][0], bl[g * 2 + 1][0],
                        bl[g * 2][1], bl[g * 2 + 1][1], addr + TILE_B);
            }
#pragma unroll
            for (int mf = 0; mf < 2; mf++) {
                uint32_t aaddr = sb +
                    (uint32_t)((wm * 32 + mf * 16 + lrow) * T_STRIDE + kh + lcol) * 2;
                uint32_t ah[4], al[4];
                LDSM_X4(ah[0], ah[1], ah[2], ah[3], aaddr);
                LDSM_X4(al[0], al[1], al[2], al[3], aaddr + TILE_B);
#pragma unroll
                for (int nf = 0; nf < 8; nf++) {
                    MMA16816(c[mf][nf], ah, bh[nf]);
                    MMA16816(c[mf][nf], ah, bl[nf]);
                    MMA16816(c[mf][nf], al, bh[nf]);
                }
            }
        }
    }

#pragma unroll
    for (int mf = 0; mf < 2; mf++) {
        const int row0 = mBase + wm * 32 + mf * 16 + (lane >> 2);
#pragma unroll
        for (int nf = 0; nf < 8; nf++) {
            const int col = nBase + wn * 64 + nf * 8 + (lane & 3) * 2;
            const float b0 = bias[col], b1 = bias[col + 1];
            float v00 = c[mf][nf][0] + b0, v01 = c[mf][nf][1] + b1;
            float v10 = c[mf][nf][2] + b0, v11 = c[mf][nf][3] + b1;
            if (Chi) {
                __nv_bfloat16 h00 = __float2bfloat16(v00), h01 = __float2bfloat16(v01);
                __nv_bfloat16 h10 = __float2bfloat16(v10), h11 = __float2bfloat16(v11);
                size_t o0 = (size_t)row0 * DMODEL + col, o1 = (size_t)(row0 + 8) * DMODEL + col;
                *reinterpret_cast<__nv_bfloat162*>(Chi + o0) = __nv_bfloat162(h00, h01);
                *reinterpret_cast<__nv_bfloat162*>(Chi + o1) = __nv_bfloat162(h10, h11);
                *reinterpret_cast<__nv_bfloat162*>(Clo + o0) = __nv_bfloat162(
                    __float2bfloat16(v00 - __bfloat162float(h00)),
                    __float2bfloat16(v01 - __bfloat162float(h01)));
                *reinterpret_cast<__nv_bfloat162*>(Clo + o1) = __nv_bfloat162(
                    __float2bfloat16(v10 - __bfloat162float(h10)),
                    __float2bfloat16(v11 - __bfloat162float(h11)));
            } else {
                *reinterpret_cast<float2*>(C + (size_t)row0 * DMODEL + col)       = make_float2(v00, v01);
                *reinterpret_cast<float2*>(C + (size_t)(row0 + 8) * DMODEL + col) = make_float2(v10, v11);
            }
        }
    }
}

__global__ void __launch_bounds__(256)
gemm_qkv(const __nv_bfloat16* __restrict__ Ahi, const __nv_bfloat16* __restrict__ Alo,
         const __nv_bfloat16* __restrict__ Whi, const __nv_bfloat16* __restrict__ Wlo,
         const float* __restrict__ b0, const float* __restrict__ b1, const float* __restrict__ b2,
         __nv_bfloat16* __restrict__ o0h, __nv_bfloat16* __restrict__ o0l,
         __nv_bfloat16* __restrict__ o1h, __nv_bfloat16* __restrict__ o1l,
         __nv_bfloat16* __restrict__ o2h, __nv_bfloat16* __restrict__ o2l)
{
    extern __shared__ __align__(128) char smem[];
    const int z = blockIdx.z;
    const size_t aoff = (size_t)z * MTOT * GK;
    const size_t woff = (size_t)z * DMODEL * GK;
    const float* bias = (z == 0) ? b0 : ((z == 1) ? b1 : b2);
    __nv_bfloat16* oh = (z == 0) ? o0h : ((z == 1) ? o1h : o2h);
    __nv_bfloat16* ol = (z == 0) ? o0l : ((z == 1) ? o1l : o2l);
    gemm_core(Ahi + aoff, Alo + aoff, Whi + woff, Wlo + woff,
              bias, nullptr, oh, ol, smem, blockIdx.y * 128, blockIdx.x * 128);
}

__global__ void __launch_bounds__(256)
gemm_out(const __nv_bfloat16* __restrict__ Ahi, const __nv_bfloat16* __restrict__ Alo,
         const __nv_bfloat16* __restrict__ Whi, const __nv_bfloat16* __restrict__ Wlo,
         const float* __restrict__ bias, float* __restrict__ C)
{
    extern __shared__ __align__(128) char smem[];
    gemm_core(Ahi, Alo, Whi, Wlo, bias, C, nullptr, nullptr,
              smem, blockIdx.y * 128, blockIdx.x * 128);
}

// ===========================================================================
// Fully fused attention, 512 threads (16 warps, 4x4 warp grid).
// Double-buffered K (phase 1) and V (phase 3) tiles.
// smem: S (64x516 fp32) + 6 tile buffers (Q h/l + 2-stage K/V h/l).
// ===========================================================================
#define S_STRIDE 516
#define FS_SBYTES (64 * S_STRIDE * 4)          // 132096
#define FS_TSTRIDE 72
#define FS_TILE (64 * FS_TSTRIDE)              // elems
#define FS_TILEB (FS_TILE * 2)                 // 9216 bytes
#define FS_SMEM (FS_SBYTES + 6 * FS_TILEB)     // 187392

__global__ void __launch_bounds__(512)
fused_attention(const float* __restrict__ rel_bias)
{
    extern __shared__ __align__(128) char fsmem[];
    float* S = reinterpret_cast<float*>(fsmem);
    const uint32_t sbase = smem_to_u32(fsmem);
    const uint32_t uQh = sbase + FS_SBYTES;          // Q hi  (later P hi)
    const uint32_t uQl = uQh + FS_TILEB;             // Q lo  (later P lo)
    const uint32_t uK0h = uQl + FS_TILEB;            // K/V stage0 hi
    const uint32_t uK0l = uK0h + FS_TILEB;
    const uint32_t uK1h = uK0l + FS_TILEB;           // K/V stage1 hi
    const uint32_t uK1l = uK1h + FS_TILEB;

    const int s0 = (gridDim.x - 1 - blockIdx.x) * 64;   // heavy tiles first
    const int bh = blockIdx.y;
    const int b  = bh >> 4;
    const int h  = bh & 15;
    const int tid = threadIdx.x, lane = tid & 31, wid = tid >> 5;
    const int wm = wid & 3, wn = wid >> 2;          // 4x4 warp grid

    const int lr = tid >> 3;                         // 0..63
    const int cb = (tid & 7) * 16;                   // 0..112
    const int ntiles = s0 / 64 + 1;
    const int lrow = lane & 15;
    const int lcol = (lane >> 4) * 8;

    // ---------------- Phase 1: scores -> S ----------------
    {   // Q + K0 (group 0)
        const char* gQh = (const char*)(g_Qh + ((size_t)(b * SEQ + s0 + lr)) * DMODEL + h * DK);
        const char* gQl = (const char*)(g_Ql + ((size_t)(b * SEQ + s0 + lr)) * DMODEL + h * DK);
        cp_async16(uQh + lr * 144 + cb, gQh + cb);
        cp_async16(uQl + lr * 144 + cb, gQl + cb);
        const char* gKh = (const char*)(g_Kh + ((size_t)(b * SEQ + lr)) * DMODEL + h * DK);
        const char* gKl = (const char*)(g_Kl + ((size_t)(b * SEQ + lr)) * DMODEL + h * DK);
        cp_async16(uK0h + lr * 144 + cb, gKh + cb);
        cp_async16(uK0l + lr * 144 + cb, gKl + cb);
        cp_commit();
    }
    if (ntiles > 1) {   // K1 (group 1)
        const char* gKh = (const char*)(g_Kh + ((size_t)(b * SEQ + 64 + lr)) * DMODEL + h * DK);
        const char* gKl = (const char*)(g_Kl + ((size_t)(b * SEQ + 64 + lr)) * DMODEL + h * DK);
        cp_async16(uK1h + lr * 144 + cb, gKh + cb);
        cp_async16(uK1l + lr * 144 + cb, gKl + cb);
        cp_commit();
    }

    for (int t = 0; t < ntiles; t++) {
        const int t0 = t * 64;
        if (t + 1 < ntiles) cp_wait1(); else cp_wait0();
        __syncthreads();

        const uint32_t uKh = (t & 1) ? uK1h : uK0h;
        const uint32_t uKl = (t & 1) ? uK1l : uK0l;

        float c[2][4];
#pragma unroll
        for (int nf = 0; nf < 2; nf++)
#pragma unroll
            for (int j = 0; j < 4; j++) c[nf][j] = 0.f;

#pragma unroll
        for (int k0 = 0; k0 < 64; k0 += 16) {
            uint32_t aoff = (uint32_t)((wm * 16 + lrow) * FS_TSTRIDE + k0 + lcol) * 2;
            uint32_t ah[4], al[4];
            LDSM_X4(ah[0], ah[1], ah[2], ah[3], uQh + aoff);
            LDSM_X4(al[0], al[1], al[2], al[3], uQl + aoff);
            uint32_t boff = (uint32_t)((wn * 16 + lrow) * FS_TSTRIDE + k0 + lcol) * 2;
            uint32_t bhf[2][2], blf[2][2];
            LDSM_X4(bhf[0][0], bhf[1][0], bhf[0][1], bhf[1][1], uKh + boff);
            LDSM_X4(blf[0][0], blf[1][0], blf[0][1], blf[1][1], uKl + boff);
#pragma unroll
            for (int nf = 0; nf < 2; nf++) {
                MMA16816(c[nf], ah, bhf[nf]);
                MMA16816(c[nf], ah, blf[nf]);
                MMA16816(c[nf], al, bhf[nf]);
            }
        }

        {
            const int r0 = wm * 16 + (lane >> 2);
            const int sg0 = s0 + r0, sg1 = sg0 + 8;
#pragma unroll
            for (int nf = 0; nf < 2; nf++) {
                const int col = wn * 16 + nf * 8 + (lane & 3) * 2;
                const int tg = t0 + col;
                float2 rb0 = *reinterpret_cast<const float2*>(
                    rel_bias + ((size_t)h * SEQ + sg0) * SEQ + tg);
                float2 rb1 = *reinterpret_cast<const float2*>(
                    rel_bias + ((size_t)h * SEQ + sg1) * SEQ + tg);
                float v00 = c[nf][0] * 0.125f + rb0.x; if (tg     > sg0) v00 = -INFINITY;
                float v01 = c[nf][1] * 0.125f + rb0.y; if (tg + 1 > sg0) v01 = -INFINITY;
                float v10 = c[nf][2] * 0.125f + rb1.x; if (tg     > sg1) v10 = -INFINITY;
                float v11 = c[nf][3] * 0.125f + rb1.y; if (tg + 1 > sg1) v11 = -INFINITY;
                *reinterpret_cast<float2*>(&S[r0 * S_STRIDE + tg])       = make_float2(v00, v01);
                *reinterpret_cast<float2*>(&S[(r0 + 8) * S_STRIDE + tg]) = make_float2(v10, v11);
            }
        }
        __syncthreads();

        if (t + 2 < ntiles) {
            const int tn = (t + 2) * 64;
            const uint32_t dKh = (t & 1) ? uK1h : uK0h;   // stage being freed
            const uint32_t dKl = (t & 1) ? uK1l : uK0l;
            const char* gKh = (const char*)(g_Kh + ((size_t)(b * SEQ + tn + lr)) * DMODEL + h * DK);
            const char* gKl = (const char*)(g_Kl + ((size_t)(b * SEQ + tn + lr)) * DMODEL + h * DK);
            cp_async16(dKh + lr * 144 + cb, gKh + cb);
            cp_async16(dKl + lr * 144 + cb, gKl + cb);
            cp_commit();
        }
    }

    // ---------------- Phase 2: softmax (fp32 in S; fp16 to DRAM) ------------
    const int Lt = s0 + 64;
    for (int r = wid * 4; r < wid * 4 + 4; r++) {
        const int s = s0 + r;
        const int L = s + 1;
        float* row = S + r * S_STRIDE;

        float m = -INFINITY;
        for (int ci = lane; ci < L; ci += 32) m = fmaxf(m, row[ci]);
#pragma unroll
        for (int o = 16; o; o >>= 1) m = fmaxf(m, __shfl_xor_sync(0xffffffffu, m, o));

        float sum = 0.f;
        for (int ci = lane; ci < L; ci += 32) {
            float e = __expf(row[ci] - m);
            row[ci] = e;
            sum += e;
        }
#pragma unroll
        for (int o = 16; o; o >>= 1) sum += __shfl_xor_sync(0xffffffffu, sum, o);
        const float inv = 1.f / sum;

        __half* om = g_Pm + ((size_t)bh * SEQ + s) * SEQ;
        for (int ci = lane; ci < Lt; ci += 32) {
            float p = (ci < L) ? row[ci] * inv : 0.f;
            row[ci] = p;
            om[ci] = __float2half_rn(p);
        }
    }
    __syncthreads();

    // ---------------- Phase 3: ctx = P @ V ----------------
    float c2[2][4];
#pragma unroll
    for (int nf = 0; nf < 2; nf++)
#pragma unroll
        for (int j = 0; j < 4; j++) c2[nf][j] = 0.f;

    {   // V0 (group)
        const char* gVh = (const char*)(g_Vh + ((size_t)(b * SEQ + lr)) * DMODEL + h * DK);
        const char* gVl = (const char*)(g_Vl + ((size_t)(b * SEQ + lr)) * DMODEL + h * DK);
        cp_async16(uK0h + lr * 144 + cb, gVh + cb);
        cp_async16(uK0l + lr * 144 + cb, gVl + cb);
        cp_commit();
    }
    if (ntiles > 1) {
        const char* gVh = (const char*)(g_Vh + ((size_t)(b * SEQ + 64 + lr)) * DMODEL + h * DK);
        const char* gVl = (const char*)(g_Vl + ((size_t)(b * SEQ + 64 + lr)) * DMODEL + h * DK);
        cp_async16(uK1h + lr * 144 + cb, gVh + cb);
        cp_async16(uK1l + lr * 144 + cb, gVl + cb);
        cp_commit();
    }

    __nv_bfloat16* tPh = reinterpret_cast<__nv_bfloat16*>(fsmem + FS_SBYTES);
    __nv_bfloat16* tPl = tPh + FS_TILE;

    for (int t = 0; t < ntiles; t++) {
        const int t0 = t * 64;
        if (t + 1 < ntiles) cp_wait1(); else cp_wait0();

        // convert S[:, t0:t0+64] -> tPh/tPl (each thread: 8 elems of one row)
        {
            const int pr = tid >> 3;                  // 0..63
            const int pc = (tid & 7) * 8;             // 0..56
            const float* srow = S + pr * S_STRIDE + t0 + pc;
            __nv_bfloat16* ph = tPh + pr * FS_TSTRIDE + pc;
            __nv_bfloat16* pl = tPl + pr * FS_TSTRIDE + pc;
#pragma unroll
            for (int q = 0; q < 2; q++) {
                float4 v = *reinterpret_cast<const float4*>(srow + q * 4);
                __nv_bfloat16 h0 = __float2bfloat16(v.x);
                __nv_bfloat16 h1 = __float2bfloat16(v.y);
                __nv_bfloat16 h2 = __float2bfloat16(v.z);
                __nv_bfloat16 h3 = __float2bfloat16(v.w);
                *reinterpret_cast<__nv_bfloat162*>(ph + q * 4)     = __nv_bfloat162(h0, h1);
                *reinterpret_cast<__nv_bfloat162*>(ph + q * 4 + 2) = __nv_bfloat162(h2, h3);
                *reinterpret_cast<__nv_bfloat162*>(pl + q * 4)     = __nv_bfloat162(
                    __float2bfloat16(v.x - __bfloat162float(h0)),
                    __float2bfloat16(v.y - __bfloat162float(h1)));
                *reinterpret_cast<__nv_bfloat162*>(pl + q * 4 + 2) = __nv_bfloat162(
                    __float2bfloat16(v.z - __bfloat162float(h2)),
                    __float2bfloat16(v.w - __bfloat162float(h3)));
            }
        }
        __syncthreads();

        const uint32_t uVh = (t & 1) ? uK1h : uK0h;
        const uint32_t uVl = (t & 1) ? uK1l : uK0l;

#pragma unroll
        for (int k0 = 0; k0 < 64; k0 += 16) {
            uint32_t aoff = (uint32_t)((wm * 16 + lrow) * FS_TSTRIDE + k0 + lcol) * 2;
            uint32_t ah[4], al[4];
            LDSM_X4(ah[0], ah[1], ah[2], ah[3], uQh + aoff);
            LDSM_X4(al[0], al[1], al[2], al[3], uQl + aoff);
            uint32_t boff = (uint32_t)((k0 + lrow) * FS_TSTRIDE + wn * 16 + lcol) * 2;
            uint32_t bhf[2][2], blf[2][2];
            LDSM_X4_T(bhf[0][0], bhf[0][1], bhf[1][0], bhf[1][1], uVh + boff);
            LDSM_X4_T(blf[0][0], blf[0][1], blf[1][0], blf[1][1], uVl + boff);
#pragma unroll
            for (int nf = 0; nf < 2; nf++) {
                MMA16816(c2[nf], ah, bhf[nf]);
                MMA16816(c2[nf], ah, blf[nf]);
                MMA16816(c2[nf], al, bhf[nf]);
            }
        }
        __syncthreads();

        if (t + 2 < ntiles) {
            const int tn = (t + 2) * 64;
            const uint32_t dVh = (t & 1) ? uK1h : uK0h;
            const uint32_t dVl = (t & 1) ? uK1l : uK0l;
            const char* gVh = (const char*)(g_Vh + ((size_t)(b * SEQ + tn + lr)) * DMODEL + h * DK);
            const char* gVl = (const char*)(g_Vl + ((size_t)(b * SEQ + tn + lr)) * DMODEL + h * DK);
            cp_async16(dVh + lr * 144 + cb, gVh + cb);
            cp_async16(dVl + lr * 144 + cb, gVl + cb);
            cp_commit();
        }
    }

    // ctx epilogue -> g_Ch / g_Cl
    const int r0 = wm * 16 + (lane >> 2);
#pragma unroll
    for (int nf = 0; nf < 2; nf++) {
        const int col = wn * 16 + nf * 8 + (lane & 3) * 2;
#pragma unroll
        for (int half = 0; half < 2; half++) {
            const int s = s0 + r0 + half * 8;
            const float v0 = c2[nf][half * 2], v1 = c2[nf][half * 2 + 1];
            __nv_bfloat16 h0 = __float2bfloat16(v0);
            __nv_bfloat16 h1 = __float2bfloat16(v1);
            size_t o = ((size_t)(b * SEQ + s)) * DMODEL + h * DK + col;
            *reinterpret_cast<__nv_bfloat162*>(g_Ch + o) = __nv_bfloat162(h0, h1);
            *reinterpret_cast<__nv_bfloat162*>(g_Cl + o) = __nv_bfloat162(
                __float2bfloat16(v0 - __bfloat162float(h0)),
                __float2bfloat16(v1 - __bfloat162float(h1)));
        }
    }
}

// ===========================================================================
// attn head-mean (fp16 P; causal-bounded)
// ===========================================================================
__global__ void __launch_bounds__(256)
mean_kernel(float* __restrict__ out2)
{
    const size_t idx = (size_t)blockIdx.x * 256 + threadIdx.x;
    const int b = (int)(idx >> 18);
    const int r = (int)(idx & 262143);
    const int s = r >> 9;
    const int t = r & 511;
    if (t > s) { out2[idx] = 0.f; return; }
    float sum = 0.f;
#pragma unroll
    for (int h = 0; h < NHEAD; h++) {
        sum += __half2float(g_Pm[((size_t)(b * NHEAD + h) * SEQ + s) * SEQ + t]);
    }
    out2[idx] = sum * (1.f / NHEAD);
}

// ===========================================================================
// Launch
// ===========================================================================
extern "C" void kernel_launch(void* const* d_in, const int* in_sizes, int n_in,
                              void* d_out, int out_size)
{
    const float* query = (const float*)d_in[0];
    const float* key   = (const float*)d_in[1];
    const float* value = (const float*)d_in[2];
    const float* wq_w  = (const float*)d_in[3];
    const float* wq_b  = (const float*)d_in[4];
    const float* wk_w  = (const float*)d_in[5];
    const float* wk_b  = (const float*)d_in[6];
    const float* wv_w  = (const float*)d_in[7];
    const float* wv_b  = (const float*)d_in[8];
    const float* wo_w  = (const float*)d_in[9];
    const float* wo_b  = (const float*)d_in[10];
    const float* rel_bias = (const float*)d_in[11];

    float* out  = (float*)d_out;
    const size_t out1_elems = (size_t)MTOT * DMODEL;
    const size_t out2_elems = (size_t)BATCH * SEQ * SEQ;
    float* out2 = out + out1_elems;

    __nv_bfloat16 *ahi, *alo, *whi, *wlo, *qh, *ql, *kh, *kl, *vh, *vl, *ch, *cl;
    cudaGetSymbolAddress((void**)&ahi, g_Ahi);
    cudaGetSymbolAddress((void**)&alo, g_Alo);
    cudaGetSymbolAddress((void**)&whi, g_Whi);
    cudaGetSymbolAddress((void**)&wlo, g_Wlo);
    cudaGetSymbolAddress((void**)&qh, g_Qh);
    cudaGetSymbolAddress((void**)&ql, g_Ql);
    cudaGetSymbolAddress((void**)&kh, g_Kh);
    cudaGetSymbolAddress((void**)&kl, g_Kl);
    cudaGetSymbolAddress((void**)&vh, g_Vh);
    cudaGetSymbolAddress((void**)&vl, g_Vl);
    cudaGetSymbolAddress((void**)&ch, g_Ch);
    cudaGetSymbolAddress((void**)&cl, g_Cl);

    cudaFuncSetAttribute(fused_attention,
                         cudaFuncAttributeMaxDynamicSharedMemorySize, FS_SMEM);
    cudaFuncSetAttribute(gemm_qkv,
                         cudaFuncAttributeMaxDynamicSharedMemorySize, GEMM_SMEM);
    cudaFuncSetAttribute(gemm_out,
                         cudaFuncAttributeMaxDynamicSharedMemorySize, GEMM_SMEM);

    const int nA4 = MTOT * DMODEL / 4;
    const int nW4 = DMODEL * DMODEL / 4;
    const size_t wstride = (size_t)DMODEL * DMODEL;

    split3_bf16<<<dim3(nA4 / 256, 3), 256>>>(query, key, value, ahi, alo, nA4);
    split4_bf16<<<dim3(nW4 / 256, 4), 256>>>(wq_w, wk_w, wv_w, wo_w, whi, wlo, nW4);

    gemm_qkv<<<dim3(DMODEL / 128, MTOT / 128, 3), 256, GEMM_SMEM>>>(
        ahi, alo, whi, wlo, wq_b, wk_b, wv_b, qh, ql, kh, kl, vh, vl);

    fused_attention<<<dim3(SEQ / 64, BH), 512, FS_SMEM>>>(rel_bias);

    if ((size_t)out_size >= out1_elems + out2_elems) {
        mean_kernel<<<(unsigned)(out2_elems / 256), 256>>>(out2);
    }

    gemm_out<<<dim3(DMODEL / 128, MTOT / 128), 256, GEMM_SMEM>>>(
        ch, cl, whi + 3 * wstride, wlo + 3 * wstride, wo_b, out);
}